// round 11
// baseline (speedup 1.0000x reference)
#include <cuda_runtime.h>
#include <cuda_fp16.h>
#include <math.h>
#include <stdint.h>

// Problem constants
#define Bb   1024
#define Uu   8
#define Ss   50
#define Ll   200
#define Ff   4
#define Ee   32
#define Dd   128      // F*E
#define UE   256      // U*E
#define G4   512      // 4*D
#define NEGV -1000000000.0f

// ---------------- scratch (static device globals) ---------------------------
__device__ float  g_user_e[Bb * UE];          // (B,256)
__device__ float  g_user_t[Bb * UE];          // tf32-rounded copy
__device__ float  g_stx   [Bb * Ss * Dd];     // (B,50,128) tf32-rounded
__device__ float  g_xW    [Bb * Ss * G4];     // (B,50,512) x@W+b (fp32)
__device__ float  g_hs    [Bb * Ss * Dd];     // LSTM outputs (tf32-rounded)
__device__ float  g_qkv   [Bb * Ss * 384];    // fused q|k|v
__device__ float  g_att   [Bb * Ss * Dd];     // attn out, pre-Wo (tf32-rounded)
__device__ float  g_stm   [Bb * Ss * Dd];     // MHA out (post-Wo)
__device__ float  g_qvec  [Bb * Dd];
__device__ float  g_short [Bb * Dd];
__device__ float  g_long  [Bb * Dd];
__device__ __half g_Uh    [G4 * Dd];          // U^T as fp16: [n=512][k=128]
__device__ float  g_Wr    [Dd * G4];          // tf32-rounded lstm_W
__device__ float  g_Wqkv  [Dd * 384];         // tf32-rounded packed Wq|Wk|Wv
__device__ float  g_Wor   [Dd * Dd];          // tf32-rounded Wo
__device__ float  g_W1r   [UE * Dd];          // tf32-rounded W1

__device__ __forceinline__ float sigm(float x) { return 1.0f / (1.0f + __expf(-x)); }

__device__ __forceinline__ float tanh_mufu(float x) {
    float y;
    asm("tanh.approx.f32 %0, %1;" : "=f"(y) : "f"(x));
    return y;
}
__device__ __forceinline__ float sigm_mufu(float x) {
    return fmaf(0.5f, tanh_mufu(0.5f * x), 0.5f);
}

__device__ __forceinline__ float to_tf32(float x) {
    uint32_t u;
    asm("cvt.rna.tf32.f32 %0, %1;" : "=r"(u) : "f"(x));
    return __uint_as_float(u);
}

__device__ __forceinline__ void cp16(void* smem, const void* g) {
    uint32_t s = (uint32_t)__cvta_generic_to_shared(smem);
    asm volatile("cp.async.ca.shared.global [%0], [%1], 16;" :: "r"(s), "l"(g));
}

__device__ __forceinline__ void mma_tf32(float* c, const uint32_t* a, const uint32_t* b) {
    asm volatile(
        "mma.sync.aligned.m16n8k8.row.col.f32.tf32.tf32.f32 "
        "{%0,%1,%2,%3}, {%4,%5,%6,%7}, {%8,%9}, {%0,%1,%2,%3};"
        : "+f"(c[0]), "+f"(c[1]), "+f"(c[2]), "+f"(c[3])
        : "r"(a[0]), "r"(a[1]), "r"(a[2]), "r"(a[3]), "r"(b[0]), "r"(b[1]));
}

__device__ __forceinline__ void mma_f16(float* c, const uint32_t* a, const uint32_t* b) {
    asm volatile(
        "mma.sync.aligned.m16n8k16.row.col.f32.f16.f16.f32 "
        "{%0,%1,%2,%3}, {%4,%5,%6,%7}, {%8,%9}, {%0,%1,%2,%3};"
        : "+f"(c[0]), "+f"(c[1]), "+f"(c[2]), "+f"(c[3])
        : "r"(a[0]), "r"(a[1]), "r"(a[2]), "r"(a[3]), "r"(b[0]), "r"(b[1]));
}

__device__ __forceinline__ void ldsm_x4(uint32_t& r0, uint32_t& r1, uint32_t& r2,
                                        uint32_t& r3, uint32_t addr) {
    asm volatile("ldmatrix.sync.aligned.m8n8.x4.shared.b16 {%0,%1,%2,%3}, [%4];"
                 : "=r"(r0), "=r"(r1), "=r"(r2), "=r"(r3) : "r"(addr));
}

__device__ __forceinline__ void ldsm_x2(uint32_t& r0, uint32_t& r1, uint32_t addr) {
    asm volatile("ldmatrix.sync.aligned.m8n8.x2.shared.b16 {%0,%1}, [%2];"
                 : "=r"(r0), "=r"(r1) : "r"(addr));
}

// ---------------- 1) embedding gathers --------------------------------------
__global__ void gather_kernel(const int* __restrict__ up, const int* __restrict__ stb,
                              const float* __restrict__ emb) {
    int idx = blockIdx.x * blockDim.x + threadIdx.x;
    const int n1 = Bb * UE;
    if (idx < n1) {
        int b = idx / UE, r = idx % UE;
        int u = r / Ee, e = r % Ee;
        float v = emb[up[b * Uu + u] * Ee + e];
        g_user_e[idx] = v;
        g_user_t[idx] = to_tf32(v);
    }
    int idx2 = idx - n1;
    if (idx2 >= 0 && idx2 < Bb * Ss * Dd) {
        int e = idx2 & (Ee - 1);
        int t = idx2 / Ee;            // (b*S+s)*F + f
        int f = t & (Ff - 1);
        int bs = t / Ff;              // b*S+s
        g_stx[idx2] = to_tf32(emb[stb[bs * Ff + f] * Ee + e]);
    }
}

// ---------------- 2) weight repacks ----------------------------------------
__global__ void repackU_kernel(const float* __restrict__ Uw) {
    int idx = blockIdx.x * blockDim.x + threadIdx.x;   // 65536
    if (idx >= G4 * Dd) return;
    int n = idx >> 7, k = idx & 127;
    g_Uh[idx] = __float2half(Uw[k * G4 + n]);
}

__global__ void repackW_kernel(const float* __restrict__ lstm_W,
                               const float* __restrict__ Wq,
                               const float* __restrict__ Wk,
                               const float* __restrict__ Wv,
                               const float* __restrict__ Wo,
                               const float* __restrict__ W1) {
    int idx = blockIdx.x * blockDim.x + threadIdx.x;
    if (idx < Dd * G4) {
        g_Wr[idx] = to_tf32(lstm_W[idx]);
        return;
    }
    int j = idx - Dd * G4;
    if (j < Dd * 384) {
        int k = j / 384, n = j % 384;
        float v = (n < 128) ? Wq[k * Dd + n]
                : (n < 256) ? Wk[k * Dd + (n - 128)]
                            : Wv[k * Dd + (n - 256)];
        g_Wqkv[j] = to_tf32(v);
        return;
    }
    j -= Dd * 384;
    if (j < Dd * Dd) { g_Wor[j] = to_tf32(Wo[j]); return; }
    j -= Dd * Dd;
    if (j < UE * Dd) g_W1r[j] = to_tf32(W1[j]);
}

// ---------------- tf32 tensor-core GEMM: C[M,N]=A[M,K]@W[K,N] (+bias) -------
__global__ __launch_bounds__(256, 2) void gemm_tf32(
    const float* __restrict__ A, const float* __restrict__ W,
    const float* __restrict__ bias, float* __restrict__ C,
    int M, int N, int K) {
    __shared__ float As[128][36];
    __shared__ float Bs[32][136];
    int tid = threadIdx.x;
    int lane = tid & 31, warp = tid >> 5;
    int wm = warp >> 1, wn = warp & 1;
    int g = lane >> 2, tig = lane & 3;
    int m0 = blockIdx.y * 128, n0 = blockIdx.x * 128;

    float c[2][8][4];
#pragma unroll
    for (int i = 0; i < 2; i++)
#pragma unroll
        for (int j = 0; j < 8; j++)
#pragma unroll
            for (int l = 0; l < 4; l++) c[i][j][l] = 0.f;

    for (int k0 = 0; k0 < K; k0 += 32) {
        if (k0) __syncthreads();
#pragma unroll
        for (int i = 0; i < 4; i++) {
            int idx = tid + i * 256;
            int r = idx >> 3, c4 = (idx & 7) * 4;
            cp16(&As[r][c4], &A[(m0 + r) * K + k0 + c4]);
        }
#pragma unroll
        for (int i = 0; i < 4; i++) {
            int idx = tid + i * 256;
            int r = idx >> 5, c4 = (idx & 31) * 4;
            cp16(&Bs[r][c4], &W[(k0 + r) * N + n0 + c4]);
        }
        asm volatile("cp.async.commit_group;");
        asm volatile("cp.async.wait_group 0;");
        __syncthreads();

#pragma unroll
        for (int kk = 0; kk < 32; kk += 8) {
            uint32_t a[2][4], b[8][2];
#pragma unroll
            for (int mt = 0; mt < 2; mt++) {
                int mr = wm * 32 + mt * 16;
                a[mt][0] = __float_as_uint(As[mr + g][kk + tig]);
                a[mt][1] = __float_as_uint(As[mr + g + 8][kk + tig]);
                a[mt][2] = __float_as_uint(As[mr + g][kk + tig + 4]);
                a[mt][3] = __float_as_uint(As[mr + g + 8][kk + tig + 4]);
            }
#pragma unroll
            for (int nt = 0; nt < 8; nt++) {
                int nc = wn * 64 + nt * 8 + g;
                b[nt][0] = __float_as_uint(Bs[kk + tig][nc]);
                b[nt][1] = __float_as_uint(Bs[kk + tig + 4][nc]);
            }
#pragma unroll
            for (int mt = 0; mt < 2; mt++)
#pragma unroll
                for (int nt = 0; nt < 8; nt++)
                    mma_tf32(c[mt][nt], a[mt], b[nt]);
        }
    }

#pragma unroll
    for (int mt = 0; mt < 2; mt++) {
        int row = m0 + wm * 32 + mt * 16 + g;
#pragma unroll
        for (int nt = 0; nt < 8; nt++) {
            int col = n0 + wn * 64 + nt * 8 + 2 * tig;
            float bx = 0.f, by = 0.f;
            if (bias) { bx = bias[col]; by = bias[col + 1]; }
            float2 o0 = make_float2(c[mt][nt][0] + bx, c[mt][nt][1] + by);
            float2 o1 = make_float2(c[mt][nt][2] + bx, c[mt][nt][3] + by);
            *(float2*)&C[row * N + col] = o0;
            *(float2*)&C[(row + 8) * N + col] = o1;
        }
    }
}

// ---------------- 3) LSTM: 2-CTA cluster, full m16 rows, n-split ------------
// 64 clusters x 2 CTAs = 128 CTAs. Cluster handles 16 batch rows; CTA rank q
// owns d-cols [q*64, q*64+64) across all 4 gates (U slice: 256 n-rows, 70KB
// smem). 256 threads (8 warps): warp w owns d-cols [q*64+w*8, +8) x 4 gates
// -> 32 mma/warp/step with ALL 16 rows live => 64 mma/SMSP/step (HALF of the
// single-CTA designs). Each lane's acc c0..c3 = 4 gate pre-acts of its 4
// cells (rows gid & gid+8, cols dg, dg+1). h halves exchanged via
// st.shared::cluster (mapa, precomputed); ONE cluster barrier per step.
#define UT_STRIDE 136          // fp16 elems per Ut row (conflict-free ldmatrix)
#define HB_STRIDE 136
#define LSTM_SMEM_BYTES (256 * UT_STRIDE * 2 + 2 * 16 * HB_STRIDE * 2)

__global__ __launch_bounds__(256, 1) void lstm_cluster_mma(
    const float* __restrict__ xW, float* __restrict__ hs) {
    extern __shared__ __align__(16) char smem_raw[];
    __half* Ut  = (__half*)smem_raw;                          // [256][136]
    __half* hb0 = (__half*)(smem_raw + 256 * UT_STRIDE * 2);  // [16][136]
    __half* hb1 = hb0 + 16 * HB_STRIDE;                       // [16][136]

    int tid = threadIdx.x;
    int lane = tid & 31, warp = tid >> 5;                     // warp 0..7
    uint32_t q;
    asm("mov.u32 %0, %%cluster_ctarank;" : "=r"(q));          // 0 or 1
    int b0 = (blockIdx.x >> 1) * 16;

    // ---- stage this CTA's U slice (global n = gate*128 + q*64 + j) ----
    for (int i = tid; i < 256 * Dd / 8; i += 256) {           // 4096 16B chunks
        int nl = i >> 4, c = (i & 15) * 8;                    // local row nl
        int gate = nl >> 6, j = nl & 63;
        int gn = gate * 128 + q * 64 + j;
        cp16(&Ut[nl * UT_STRIDE + c], &g_Uh[gn * Dd + c]);
    }
    for (int i = tid; i < 2 * 16 * HB_STRIDE; i += 256) hb0[i] = __float2half(0.f);
    asm volatile("cp.async.commit_group;");
    asm volatile("cp.async.wait_group 0;");
    __syncthreads();
    asm volatile("barrier.cluster.arrive.aligned;" ::: "memory");
    asm volatile("barrier.cluster.wait.aligned;" ::: "memory");

    // ---- ldmatrix A base addresses (16 live rows, both buffers) ----
    int arow = lane & 15;
    int akofs = (lane >> 4) * 8;
    uint32_t aAddr0 = (uint32_t)__cvta_generic_to_shared(hb0) +
                      (arow * HB_STRIDE + akofs) * 2;
    uint32_t aAddr1 = (uint32_t)__cvta_generic_to_shared(hb1) +
                      (arow * HB_STRIDE + akofs) * 2;

    // ---- preload U fragments: warp w, gate g -> local rows g*64 + w*8 + bn --
    uint32_t ut_base = (uint32_t)__cvta_generic_to_shared(Ut);
    int bn = lane & 7;
    int bkofs = ((lane >> 3) & 1) * 8;
    uint32_t bf[8][4][2];                                     // [kt][gate][2]
#pragma unroll
    for (int g = 0; g < 4; g++) {
        uint32_t base = ut_base +
            ((g * 64 + warp * 8 + bn) * UT_STRIDE + bkofs) * 2;
#pragma unroll
        for (int kt = 0; kt < 8; kt++)
            ldsm_x2(bf[kt][g][0], bf[kt][g][1], base + kt * 32);
    }

    int gid = lane >> 2, tig = lane & 3;
    int dg = q * 64 + warp * 8 + 2 * tig;                     // this lane's col pair
    int r0 = gid, r1 = gid + 8;                               // this lane's 2 rows
    const float* xrow0 = xW + (size_t)((b0 + r0) * Ss) * G4 + dg;
    const float* xrow1 = xW + (size_t)((b0 + r1) * Ss) * G4 + dg;
    float* hsrow0 = hs + (size_t)((b0 + r0) * Ss) * Dd + dg;
    float* hsrow1 = hs + (size_t)((b0 + r1) * Ss) * Dd + dg;

    // local h-slot addresses + mapa'd peer addresses (both buffers, both rows)
    uint32_t l0a = (uint32_t)__cvta_generic_to_shared(&hb0[r0 * HB_STRIDE + dg]);
    uint32_t l0b = (uint32_t)__cvta_generic_to_shared(&hb0[r1 * HB_STRIDE + dg]);
    uint32_t l1a = (uint32_t)__cvta_generic_to_shared(&hb1[r0 * HB_STRIDE + dg]);
    uint32_t l1b = (uint32_t)__cvta_generic_to_shared(&hb1[r1 * HB_STRIDE + dg]);
    uint32_t peer = 1 - q;
    uint32_t p0a, p0b, p1a, p1b;
    asm("mapa.shared::cluster.u32 %0, %1, %2;" : "=r"(p0a) : "r"(l0a), "r"(peer));
    asm("mapa.shared::cluster.u32 %0, %1, %2;" : "=r"(p0b) : "r"(l0b), "r"(peer));
    asm("mapa.shared::cluster.u32 %0, %1, %2;" : "=r"(p1a) : "r"(l1a), "r"(peer));
    asm("mapa.shared::cluster.u32 %0, %1, %2;" : "=r"(p1b) : "r"(l1b), "r"(peer));

    float cc[2][2] = {{0.f, 0.f}, {0.f, 0.f}};
    float2 xc0[4], xc1[4], xn0[4], xn1[4];
#pragma unroll
    for (int g = 0; g < 4; g++) {
        xc0[g] = *(const float2*)&xrow0[g * 128];
        xc1[g] = *(const float2*)&xrow1[g * 128];
        xn0[g] = xc0[g]; xn1[g] = xc1[g];
    }

    int p = 0;
    for (int step = 0; step < Ss; step++) {
        if (step + 1 < Ss) {
            const float* xb0 = xrow0 + (step + 1) * G4;
            const float* xb1 = xrow1 + (step + 1) * G4;
#pragma unroll
            for (int g = 0; g < 4; g++) {
                xn0[g] = *(const float2*)&xb0[g * 128];
                xn1[g] = *(const float2*)&xb1[g * 128];
            }
        }

        // ---- mma: z = h(16 rows) @ U(this CTA's 64 cols x 4 gates) ----
        float acc[4][4];
#pragma unroll
        for (int g = 0; g < 4; g++)
#pragma unroll
            for (int j = 0; j < 4; j++) acc[g][j] = 0.f;
        uint32_t aAddr = p ? aAddr1 : aAddr0;
#pragma unroll
        for (int kt = 0; kt < 8; kt++) {
            uint32_t a[4];
            ldsm_x4(a[0], a[1], a[2], a[3], aAddr + kt * 32);
#pragma unroll
            for (int g = 0; g < 4; g++)
                mma_f16(acc[g], a, bf[kt][g]);
        }

        // ---- epilogue: 4 cells (rows r0 via c0/c1, r1 via c2/c3) ----
        float h00, h01, h10, h11;
        {
            float iv0 = sigm_mufu(acc[0][0] + xc0[0].x);
            float iv1 = sigm_mufu(acc[0][1] + xc0[0].y);
            float fv0 = sigm_mufu(acc[1][0] + xc0[1].x);
            float fv1 = sigm_mufu(acc[1][1] + xc0[1].y);
            float gv0 = tanh_mufu(acc[2][0] + xc0[2].x);
            float gv1 = tanh_mufu(acc[2][1] + xc0[2].y);
            float ov0 = sigm_mufu(acc[3][0] + xc0[3].x);
            float ov1 = sigm_mufu(acc[3][1] + xc0[3].y);
            cc[0][0] = fv0 * cc[0][0] + iv0 * gv0;
            cc[0][1] = fv1 * cc[0][1] + iv1 * gv1;
            h00 = ov0 * tanh_mufu(cc[0][0]);
            h01 = ov1 * tanh_mufu(cc[0][1]);
        }
        {
            float iv0 = sigm_mufu(acc[0][2] + xc1[0].x);
            float iv1 = sigm_mufu(acc[0][3] + xc1[0].y);
            float fv0 = sigm_mufu(acc[1][2] + xc1[1].x);
            float fv1 = sigm_mufu(acc[1][3] + xc1[1].y);
            float gv0 = tanh_mufu(acc[2][2] + xc1[2].x);
            float gv1 = tanh_mufu(acc[2][3] + xc1[2].y);
            float ov0 = sigm_mufu(acc[3][2] + xc1[3].x);
            float ov1 = sigm_mufu(acc[3][3] + xc1[3].y);
            cc[1][0] = fv0 * cc[1][0] + iv0 * gv0;
            cc[1][1] = fv1 * cc[1][1] + iv1 * gv1;
            h10 = ov0 * tanh_mufu(cc[1][0]);
            h11 = ov1 * tanh_mufu(cc[1][1]);
        }

        // write h to the OTHER buffer: local + peer (DSMEM)
        __half2 v0 = __floats2half2_rn(h00, h01);
        __half2 v1 = __floats2half2_rn(h10, h11);
        uint32_t la = p ? l0a : l1a, lb = p ? l0b : l1b;
        uint32_t ra = p ? p0a : p1a, rb = p ? p0b : p1b;
        uint32_t u0 = *(uint32_t*)&v0, u1 = *(uint32_t*)&v1;
        asm volatile("st.shared.b32 [%0], %1;" :: "r"(la), "r"(u0) : "memory");
        asm volatile("st.shared.b32 [%0], %1;" :: "r"(lb), "r"(u1) : "memory");
        asm volatile("st.shared::cluster.b32 [%0], %1;" :: "r"(ra), "r"(u0) : "memory");
        asm volatile("st.shared::cluster.b32 [%0], %1;" :: "r"(rb), "r"(u1) : "memory");
        *(float2*)&hsrow0[step * Dd] = make_float2(to_tf32(h00), to_tf32(h01));
        *(float2*)&hsrow1[step * Dd] = make_float2(to_tf32(h10), to_tf32(h11));

        asm volatile("barrier.cluster.arrive.aligned;" ::: "memory");
        asm volatile("barrier.cluster.wait.aligned;" ::: "memory");
        p ^= 1;
#pragma unroll
        for (int g = 0; g < 4; g++) { xc0[g] = xn0[g]; xc1[g] = xn1[g]; }
    }
}

// ---------------- 4) MHA core: one block per (b, head) ----------------------
__global__ __launch_bounds__(128) void mha_kernel() {
    int bh = blockIdx.x;
    int b = bh >> 2, h = bh & 3;
    __shared__ float qs[Ss][Ee], ks[Ss][Ee], vs[Ss][Ee];
    __shared__ float sc[Ss][52];
    int t = threadIdx.x;
    for (int idx = t; idx < Ss * Ee; idx += 128) {
        int s = idx >> 5, e = idx & 31;
        int base = (b * Ss + s) * 384 + h * Ee + e;
        qs[s][e] = g_qkv[base];
        ks[s][e] = g_qkv[base + 128];
        vs[s][e] = g_qkv[base + 256];
    }
    __syncthreads();
    const float scale = 0.17677669529663687f;  // 1/sqrt(32)
    for (int idx = t; idx < Ss * Ss; idx += 128) {
        int r = idx / Ss, c = idx % Ss;
        float a = 0.f;
#pragma unroll
        for (int e = 0; e < Ee; e++) a += qs[r][e] * ks[c][e];
        sc[r][c] = a * scale;
    }
    __syncthreads();
    if (t < Ss) {
        float mx = -3.4e38f;
        for (int c = 0; c < Ss; c++) mx = fmaxf(mx, sc[t][c]);
        float sm = 0.f;
        for (int c = 0; c < Ss; c++) { float e = __expf(sc[t][c] - mx); sc[t][c] = e; sm += e; }
        float inv = 1.f / sm;
        for (int c = 0; c < Ss; c++) sc[t][c] *= inv;
    }
    __syncthreads();
    for (int idx = t; idx < Ss * Ee; idx += 128) {
        int s = idx >> 5, e = idx & 31;
        float a = 0.f;
        for (int c = 0; c < Ss; c++) a += sc[s][c] * vs[c][e];
        g_att[(b * Ss + s) * Dd + h * Ee + e] = to_tf32(a);
    }
}

// ---------------- 5) short-term attention pooling (parallel softmax) --------
__global__ __launch_bounds__(128) void shortpool_kernel() {
    int b = blockIdx.x;
    __shared__ float qv[Dd];
    __shared__ float sc[64];
    __shared__ float red4[4];
    int t = threadIdx.x;
    qv[t] = g_qvec[b * Dd + t];
    if (t >= Ss && t < 64) sc[t] = -3.4e38f;
    __syncthreads();
    if (t < Ss) {
        const float* row = &g_stm[(b * Ss + t) * Dd];
        float a = 0.f;
        for (int k = 0; k < Dd; k++) a += row[k] * qv[k];
        sc[t] = a;
    }
    __syncthreads();
    if (t < 64) {
        float v = sc[t];
#pragma unroll
        for (int ofs = 16; ofs >= 1; ofs >>= 1)
            v = fmaxf(v, __shfl_xor_sync(0xFFFFFFFFu, v, ofs));
        if ((t & 31) == 0) red4[t >> 5] = v;
    }
    __syncthreads();
    float mx = fmaxf(red4[0], red4[1]);
    float ev = (t < Ss) ? __expf(sc[t] - mx) : 0.f;
    if (t < 64) sc[t] = ev;
    __syncthreads();
    if (t < 64) {
        float v = sc[t];
#pragma unroll
        for (int ofs = 16; ofs >= 1; ofs >>= 1)
            v += __shfl_xor_sync(0xFFFFFFFFu, v, ofs);
        if ((t & 31) == 0) red4[2 + (t >> 5)] = v;
    }
    __syncthreads();
    float inv = 1.f / (red4[2] + red4[3]);
    float a = 0.f;
    for (int s = 0; s < Ss; s++) a += sc[s] * g_stm[(b * Ss + s) * Dd + t];
    g_short[b * Dd + t] = a * inv;
}

// ---------------- 6) long-term field attention (dedup mask) -----------------
__global__ __launch_bounds__(256) void longterm_kernel(const int* __restrict__ ltb,
                                                       const float* __restrict__ emb,
                                                       const float* __restrict__ Wt,
                                                       const float* __restrict__ bt) {
    int bi = blockIdx.x;
    int b = bi >> 2, fi = bi & 3;
    __shared__ int   ids[Ll];
    __shared__ float vecs[Ll][Ee];
    __shared__ float sc[Ll];
    __shared__ float uv[Ee];
    __shared__ float part[8][Ee];
    __shared__ float red[256];
    int t = threadIdx.x;
    if (t < Ll) ids[t] = ltb[(b * Ll + t) * Ff + fi];
    __syncthreads();
    for (int idx = t; idx < Ll * Ee; idx += 256) {
        int l = idx >> 5, e = idx & 31;
        vecs[l][e] = emb[ids[l] * Ee + e];
    }
    {
        int e = t & 31, g = t >> 5;
        float a = 0.f;
        for (int k = g * 32; k < g * 32 + 32; k++)
            a += g_user_e[b * UE + k] * Wt[(fi * UE + k) * Ee + e];
        part[g][e] = a;
    }
    __syncthreads();
    if (t < Ee) {
        float a = bt[fi * Ee + t];
        for (int g = 0; g < 8; g++) a += part[g][t];
        uv[t] = a;
    }
    __syncthreads();
    if (t < Ll) {
        int mid = ids[t];
        bool keep = true;
        for (int j = 0; j < t; j++) if (ids[j] == mid) { keep = false; break; }
        float a = 0.f;
#pragma unroll
        for (int e = 0; e < Ee; e++) a += vecs[t][e] * uv[e];
        sc[t] = keep ? a : NEGV;
    }
    __syncthreads();
    red[t] = (t < Ll) ? sc[t] : -3.4e38f;
    __syncthreads();
    for (int ofs = 128; ofs >= 1; ofs >>= 1) {
        if (t < ofs) red[t] = fmaxf(red[t], red[t + ofs]);
        __syncthreads();
    }
    float mx = red[0];
    __syncthreads();
    float ev = (t < Ll) ? __expf(sc[t] - mx) : 0.f;
    if (t < Ll) sc[t] = ev;
    red[t] = ev;
    __syncthreads();
    for (int ofs = 128; ofs >= 1; ofs >>= 1) {
        if (t < ofs) red[t] += red[t + ofs];
        __syncthreads();
    }
    float inv = 1.f / red[0];
    __syncthreads();
    {
        int e = t & 31, g = t >> 5;
        float a = 0.f;
        for (int l = g; l < Ll; l += 8) a += sc[l] * vecs[l][e];
        part[g][e] = a;
    }
    __syncthreads();
    if (t < Ee) {
        float a = 0.f;
        for (int g = 0; g < 8; g++) a += part[g][t];
        g_long[b * Dd + fi * Ee + t] = a * inv;
    }
}

// ---------------- 7) final gate + mix ---------------------------------------
__global__ __launch_bounds__(128) void gate_kernel(
    const float* __restrict__ Wu, const float* __restrict__ bu,
    const float* __restrict__ Wsg, const float* __restrict__ bsg,
    const float* __restrict__ Wl, const float* __restrict__ bl,
    float* __restrict__ out) {
    int b = blockIdx.x, d = threadIdx.x;
    __shared__ float ue[UE], sh[Dd], lg[Dd];
    ue[d] = g_user_e[b * UE + d];
    ue[d + 128] = g_user_e[b * UE + 128 + d];
    sh[d] = g_short[b * Dd + d];
    lg[d] = g_long[b * Dd + d];
    __syncthreads();
    float a = bu[d] + bsg[d] + bl[d];
    for (int k = 0; k < UE; k++) a += ue[k] * Wu[k * Dd + d];
    for (int k = 0; k < Dd; k++) a += sh[k] * Wsg[k * Dd + d] + lg[k] * Wl[k * Dd + d];
    float g = sigm(a);
    out[b * Dd + d] = (1.f - g) * lg[d] + g * sh[d];
}

// ---------------- host ------------------------------------------------------
static float* sym(const void* s) {
    void* p = nullptr;
    cudaGetSymbolAddress(&p, s);
    return (float*)p;
}

extern "C" void kernel_launch(void* const* d_in, const int* in_sizes, int n_in,
                              void* d_out, int out_size) {
    const int*   up     = (const int*)d_in[0];
    const int*   stb    = (const int*)d_in[1];
    const int*   ltb    = (const int*)d_in[2];
    const float* emb    = (const float*)d_in[3];
    const float* lstm_W = (const float*)d_in[4];
    const float* lstm_U = (const float*)d_in[5];
    const float* lstm_b = (const float*)d_in[6];
    const float* Wq     = (const float*)d_in[7];
    const float* Wk     = (const float*)d_in[8];
    const float* Wv     = (const float*)d_in[9];
    const float* Wo     = (const float*)d_in[10];
    const float* W1     = (const float*)d_in[11];
    const float* b1     = (const float*)d_in[12];
    const float* Wt     = (const float*)d_in[13];
    const float* bt     = (const float*)d_in[14];
    const float* Wu     = (const float*)d_in[15];
    const float* bu     = (const float*)d_in[16];
    const float* Wsg    = (const float*)d_in[17];
    const float* bsg    = (const float*)d_in[18];
    const float* Wl     = (const float*)d_in[19];
    const float* bl     = (const float*)d_in[20];
    float* out = (float*)d_out;

    float* p_user  = sym(g_user_e);
    float* p_usert = sym(g_user_t);
    float* p_stx   = sym(g_stx);
    float* p_xW    = sym(g_xW);
    float* p_hs    = sym(g_hs);
    float* p_qkv   = sym(g_qkv);
    float* p_att   = sym(g_att);
    float* p_stm   = sym(g_stm);
    float* p_qvec  = sym(g_qvec);
    float* p_Wr    = sym(g_Wr);
    float* p_Wqkv  = sym(g_Wqkv);
    float* p_Wor   = sym(g_Wor);
    float* p_W1r   = sym(g_W1r);

    const int MBS = Bb * Ss;  // 51200

    // idempotent, every call (no static guards)
    cudaFuncSetAttribute(lstm_cluster_mma,
                         cudaFuncAttributeMaxDynamicSharedMemorySize,
                         LSTM_SMEM_BYTES);

    // 1) gathers + weight repacks
    {
        int total = Bb * UE + Bb * Ss * Dd;
        gather_kernel<<<(total + 255) / 256, 256>>>(up, stb, emb);
        repackU_kernel<<<(G4 * Dd + 255) / 256, 256>>>(lstm_U);
        int wtotal = Dd * G4 + Dd * 384 + Dd * Dd + UE * Dd;
        repackW_kernel<<<(wtotal + 255) / 256, 256>>>(lstm_W, Wq, Wk, Wv, Wo, W1);
    }
    // 2) xW = stx @ lstm_W + b   (51200 x 512 x 128) tf32
    gemm_tf32<<<dim3(G4 / 128, MBS / 128), 256>>>(p_stx, p_Wr, lstm_b, p_xW, MBS, G4, Dd);
    // 3) LSTM recurrence: 2-CTA cluster, n-split, full-row fp16 mma
    {
        cudaLaunchConfig_t cfg = {};
        cfg.gridDim = dim3(128, 1, 1);
        cfg.blockDim = dim3(256, 1, 1);
        cfg.dynamicSmemBytes = LSTM_SMEM_BYTES;
        cfg.stream = 0;
        cudaLaunchAttribute at[1];
        at[0].id = cudaLaunchAttributeClusterDimension;
        at[0].val.clusterDim.x = 2;
        at[0].val.clusterDim.y = 1;
        at[0].val.clusterDim.z = 1;
        cfg.attrs = at;
        cfg.numAttrs = 1;
        cudaLaunchKernelEx(&cfg, lstm_cluster_mma, (const float*)p_xW, p_hs);
    }
    // 4) fused QKV projection (51200 x 384 x 128) tf32
    gemm_tf32<<<dim3(384 / 128, MBS / 128), 256>>>(p_hs, p_Wqkv, nullptr, p_qkv, MBS, 384, Dd);
    // 5) attention core + output projection
    mha_kernel<<<Bb * Ff, 128>>>();
    gemm_tf32<<<dim3(Dd / 128, MBS / 128), 256>>>(p_att, p_Wor, nullptr, p_stm, MBS, Dd, Dd);
    // 6) pooling query (tf32) + short-term pooling
    gemm_tf32<<<dim3(Dd / 128, Bb / 128), 256>>>(p_usert, p_W1r, b1, p_qvec, Bb, Dd, UE);
    shortpool_kernel<<<Bb, 128>>>();
    // 7) long-term field attention
    longterm_kernel<<<Bb * Ff, 256>>>(ltb, emb, Wt, bt);
    // 8) gate + mix -> out
    gate_kernel<<<Bb, 128>>>(Wu, bu, Wsg, bsg, Wl, bl, out);
}

// round 12
// speedup vs baseline: 1.6923x; 1.6923x over previous
#include <cuda_runtime.h>
#include <cuda_fp16.h>
#include <math.h>
#include <stdint.h>

// Problem constants
#define Bb   1024
#define Uu   8
#define Ss   50
#define Ll   200
#define Ff   4
#define Ee   32
#define Dd   128      // F*E
#define UE   256      // U*E
#define G4   512      // 4*D
#define NEGV -1000000000.0f

// ---------------- scratch (static device globals) ---------------------------
__device__ float  g_user_e[Bb * UE];          // (B,256)
__device__ float  g_user_t[Bb * UE];          // tf32-rounded copy
__device__ float  g_stx   [Bb * Ss * Dd];     // (B,50,128) tf32-rounded
__device__ float  g_xW    [Bb * Ss * G4];     // (B,50,512) x@W+b (fp32)
__device__ float  g_hs    [Bb * Ss * Dd];     // LSTM outputs (tf32-rounded)
__device__ float  g_qkv   [Bb * Ss * 384];    // fused q|k|v
__device__ float  g_att   [Bb * Ss * Dd];     // attn out, pre-Wo (tf32-rounded)
__device__ float  g_stm   [Bb * Ss * Dd];     // MHA out (post-Wo)
__device__ float  g_qvec  [Bb * Dd];
__device__ float  g_short [Bb * Dd];
__device__ float  g_long  [Bb * Dd];
__device__ __half g_Uh    [G4 * Dd];          // U^T as fp16: [n=512][k=128]
__device__ float  g_Wr    [Dd * G4];          // tf32-rounded lstm_W
__device__ float  g_Wqkv  [Dd * 384];         // tf32-rounded packed Wq|Wk|Wv
__device__ float  g_Wor   [Dd * Dd];          // tf32-rounded Wo
__device__ float  g_W1r   [UE * Dd];          // tf32-rounded W1

__device__ __forceinline__ float sigm(float x) { return 1.0f / (1.0f + __expf(-x)); }

__device__ __forceinline__ float tanh_mufu(float x) {
    float y;
    asm("tanh.approx.f32 %0, %1;" : "=f"(y) : "f"(x));
    return y;
}
__device__ __forceinline__ float sigm_mufu(float x) {
    return fmaf(0.5f, tanh_mufu(0.5f * x), 0.5f);
}

__device__ __forceinline__ float to_tf32(float x) {
    uint32_t u;
    asm("cvt.rna.tf32.f32 %0, %1;" : "=r"(u) : "f"(x));
    return __uint_as_float(u);
}

__device__ __forceinline__ void cp16(void* smem, const void* g) {
    uint32_t s = (uint32_t)__cvta_generic_to_shared(smem);
    asm volatile("cp.async.ca.shared.global [%0], [%1], 16;" :: "r"(s), "l"(g));
}

__device__ __forceinline__ void mma_tf32(float* c, const uint32_t* a, const uint32_t* b) {
    asm volatile(
        "mma.sync.aligned.m16n8k8.row.col.f32.tf32.tf32.f32 "
        "{%0,%1,%2,%3}, {%4,%5,%6,%7}, {%8,%9}, {%0,%1,%2,%3};"
        : "+f"(c[0]), "+f"(c[1]), "+f"(c[2]), "+f"(c[3])
        : "r"(a[0]), "r"(a[1]), "r"(a[2]), "r"(a[3]), "r"(b[0]), "r"(b[1]));
}

__device__ __forceinline__ void mma_f16(float* c, const uint32_t* a, const uint32_t* b) {
    asm volatile(
        "mma.sync.aligned.m16n8k16.row.col.f32.f16.f16.f32 "
        "{%0,%1,%2,%3}, {%4,%5,%6,%7}, {%8,%9}, {%0,%1,%2,%3};"
        : "+f"(c[0]), "+f"(c[1]), "+f"(c[2]), "+f"(c[3])
        : "r"(a[0]), "r"(a[1]), "r"(a[2]), "r"(a[3]), "r"(b[0]), "r"(b[1]));
}

__device__ __forceinline__ void ldsm_x4(uint32_t& r0, uint32_t& r1, uint32_t& r2,
                                        uint32_t& r3, uint32_t addr) {
    asm volatile("ldmatrix.sync.aligned.m8n8.x4.shared.b16 {%0,%1,%2,%3}, [%4];"
                 : "=r"(r0), "=r"(r1), "=r"(r2), "=r"(r3) : "r"(addr));
}

__device__ __forceinline__ void ldsm_x2(uint32_t& r0, uint32_t& r1, uint32_t addr) {
    asm volatile("ldmatrix.sync.aligned.m8n8.x2.shared.b16 {%0,%1}, [%2];"
                 : "=r"(r0), "=r"(r1) : "r"(addr));
}

// ---------------- 1) embedding gathers --------------------------------------
__global__ void gather_kernel(const int* __restrict__ up, const int* __restrict__ stb,
                              const float* __restrict__ emb) {
    int idx = blockIdx.x * blockDim.x + threadIdx.x;
    const int n1 = Bb * UE;
    if (idx < n1) {
        int b = idx / UE, r = idx % UE;
        int u = r / Ee, e = r % Ee;
        float v = emb[up[b * Uu + u] * Ee + e];
        g_user_e[idx] = v;
        g_user_t[idx] = to_tf32(v);
    }
    int idx2 = idx - n1;
    if (idx2 >= 0 && idx2 < Bb * Ss * Dd) {
        int e = idx2 & (Ee - 1);
        int t = idx2 / Ee;            // (b*S+s)*F + f
        int f = t & (Ff - 1);
        int bs = t / Ff;              // b*S+s
        g_stx[idx2] = to_tf32(emb[stb[bs * Ff + f] * Ee + e]);
    }
}

// ---------------- 2) weight repacks ----------------------------------------
__global__ void repackU_kernel(const float* __restrict__ Uw) {
    int idx = blockIdx.x * blockDim.x + threadIdx.x;   // 65536
    if (idx >= G4 * Dd) return;
    int n = idx >> 7, k = idx & 127;
    g_Uh[idx] = __float2half(Uw[k * G4 + n]);
}

__global__ void repackW_kernel(const float* __restrict__ lstm_W,
                               const float* __restrict__ Wq,
                               const float* __restrict__ Wk,
                               const float* __restrict__ Wv,
                               const float* __restrict__ Wo,
                               const float* __restrict__ W1) {
    int idx = blockIdx.x * blockDim.x + threadIdx.x;
    if (idx < Dd * G4) {
        g_Wr[idx] = to_tf32(lstm_W[idx]);
        return;
    }
    int j = idx - Dd * G4;
    if (j < Dd * 384) {
        int k = j / 384, n = j % 384;
        float v = (n < 128) ? Wq[k * Dd + n]
                : (n < 256) ? Wk[k * Dd + (n - 128)]
                            : Wv[k * Dd + (n - 256)];
        g_Wqkv[j] = to_tf32(v);
        return;
    }
    j -= Dd * 384;
    if (j < Dd * Dd) { g_Wor[j] = to_tf32(Wo[j]); return; }
    j -= Dd * Dd;
    if (j < UE * Dd) g_W1r[j] = to_tf32(W1[j]);
}

// ---------------- tf32 tensor-core GEMM: C[M,N]=A[M,K]@W[K,N] (+bias) -------
__global__ __launch_bounds__(256, 2) void gemm_tf32(
    const float* __restrict__ A, const float* __restrict__ W,
    const float* __restrict__ bias, float* __restrict__ C,
    int M, int N, int K) {
    __shared__ float As[128][36];
    __shared__ float Bs[32][136];
    int tid = threadIdx.x;
    int lane = tid & 31, warp = tid >> 5;
    int wm = warp >> 1, wn = warp & 1;
    int g = lane >> 2, tig = lane & 3;
    int m0 = blockIdx.y * 128, n0 = blockIdx.x * 128;

    float c[2][8][4];
#pragma unroll
    for (int i = 0; i < 2; i++)
#pragma unroll
        for (int j = 0; j < 8; j++)
#pragma unroll
            for (int l = 0; l < 4; l++) c[i][j][l] = 0.f;

    for (int k0 = 0; k0 < K; k0 += 32) {
        if (k0) __syncthreads();
#pragma unroll
        for (int i = 0; i < 4; i++) {
            int idx = tid + i * 256;
            int r = idx >> 3, c4 = (idx & 7) * 4;
            cp16(&As[r][c4], &A[(m0 + r) * K + k0 + c4]);
        }
#pragma unroll
        for (int i = 0; i < 4; i++) {
            int idx = tid + i * 256;
            int r = idx >> 5, c4 = (idx & 31) * 4;
            cp16(&Bs[r][c4], &W[(k0 + r) * N + n0 + c4]);
        }
        asm volatile("cp.async.commit_group;");
        asm volatile("cp.async.wait_group 0;");
        __syncthreads();

#pragma unroll
        for (int kk = 0; kk < 32; kk += 8) {
            uint32_t a[2][4], b[8][2];
#pragma unroll
            for (int mt = 0; mt < 2; mt++) {
                int mr = wm * 32 + mt * 16;
                a[mt][0] = __float_as_uint(As[mr + g][kk + tig]);
                a[mt][1] = __float_as_uint(As[mr + g + 8][kk + tig]);
                a[mt][2] = __float_as_uint(As[mr + g][kk + tig + 4]);
                a[mt][3] = __float_as_uint(As[mr + g + 8][kk + tig + 4]);
            }
#pragma unroll
            for (int nt = 0; nt < 8; nt++) {
                int nc = wn * 64 + nt * 8 + g;
                b[nt][0] = __float_as_uint(Bs[kk + tig][nc]);
                b[nt][1] = __float_as_uint(Bs[kk + tig + 4][nc]);
            }
#pragma unroll
            for (int mt = 0; mt < 2; mt++)
#pragma unroll
                for (int nt = 0; nt < 8; nt++)
                    mma_tf32(c[mt][nt], a[mt], b[nt]);
        }
    }

#pragma unroll
    for (int mt = 0; mt < 2; mt++) {
        int row = m0 + wm * 32 + mt * 16 + g;
#pragma unroll
        for (int nt = 0; nt < 8; nt++) {
            int col = n0 + wn * 64 + nt * 8 + 2 * tig;
            float bx = 0.f, by = 0.f;
            if (bias) { bx = bias[col]; by = bias[col + 1]; }
            float2 o0 = make_float2(c[mt][nt][0] + bx, c[mt][nt][1] + by);
            float2 o1 = make_float2(c[mt][nt][2] + bx, c[mt][nt][3] + by);
            *(float2*)&C[row * N + col] = o0;
            *(float2*)&C[(row + 8) * N + col] = o1;
        }
    }
}

// ---------------- 3) LSTM: fp16 mma, 16 warps (4/SMSP), pipelined xW --------
// (best-passing R10 configuration, unchanged)
#define UT_STRIDE 136
#define HB_STRIDE 136
#define LSTM_ROWS 8
#define LSTM_SMEM_BYTES (G4 * UT_STRIDE * 2 + 2 * 16 * HB_STRIDE * 2)

__global__ __launch_bounds__(512, 1) void lstm_mma_kernel(
    const float* __restrict__ xW, float* __restrict__ hs) {
    extern __shared__ __align__(16) char smem_raw[];
    __half* Ut  = (__half*)smem_raw;                          // [512][136]
    __half* hb0 = (__half*)(smem_raw + G4 * UT_STRIDE * 2);   // [16][136]
    __half* hb1 = hb0 + 16 * HB_STRIDE;                       // [16][136]

    int tid = threadIdx.x;
    int lane = tid & 31, warp = tid >> 5;                     // warp 0..15
    int b0 = blockIdx.x * LSTM_ROWS;

    for (int i = tid; i < G4 * Dd / 8; i += 512) {            // 8192 16B chunks
        int n = i >> 4, c = (i & 15) * 8;
        cp16(&Ut[n * UT_STRIDE + c], &g_Uh[n * Dd + c]);
    }
    for (int i = tid; i < 2 * 16 * HB_STRIDE; i += 512) hb0[i] = __float2half(0.f);
    asm volatile("cp.async.commit_group;");
    asm volatile("cp.async.wait_group 0;");
    __syncthreads();

    int arow = lane & 15;
    int akofs = (lane >> 4) * 8;
    uint32_t aAddr0 = (uint32_t)__cvta_generic_to_shared(hb0) +
                      (arow * HB_STRIDE + akofs) * 2;
    uint32_t aAddr1 = (uint32_t)__cvta_generic_to_shared(hb1) +
                      (arow * HB_STRIDE + akofs) * 2;

    uint32_t ut_base = (uint32_t)__cvta_generic_to_shared(Ut);
    int bn = lane & 7;
    int bkofs = ((lane >> 3) & 1) * 8;
    uint32_t bf[8][4][2];                                     // [kt][gate][2]
#pragma unroll
    for (int g = 0; g < 4; g++) {
        uint32_t base = ut_base +
            ((g * 128 + warp * 8 + bn) * UT_STRIDE + bkofs) * 2;
#pragma unroll
        for (int kt = 0; kt < 8; kt++)
            ldsm_x2(bf[kt][g][0], bf[kt][g][1], base + kt * 32);
    }

    int gid = lane >> 2, tig = lane & 3;
    int col0 = warp * 8 + 2 * tig;
    const float* xrow = xW + (size_t)((b0 + gid) * Ss) * G4 + col0;
    float* hsrow = hs + (size_t)((b0 + gid) * Ss) * Dd + col0;

    float cc0 = 0.f, cc1 = 0.f;
    float2 xg_c[4], xg_n[4];
#pragma unroll
    for (int g = 0; g < 4; g++) {
        xg_c[g] = *(const float2*)&xrow[g * 128];
        xg_n[g] = xg_c[g];
    }

    int p = 0;
    for (int step = 0; step < Ss; step++) {
        if (step + 1 < Ss) {
            const float* xb = xrow + (step + 1) * G4;
#pragma unroll
            for (int g = 0; g < 4; g++)
                xg_n[g] = *(const float2*)&xb[g * 128];
        }

        float acc[4][4];
#pragma unroll
        for (int g = 0; g < 4; g++)
#pragma unroll
            for (int j = 0; j < 4; j++) acc[g][j] = 0.f;
        uint32_t aAddr = p ? aAddr1 : aAddr0;
#pragma unroll
        for (int kt = 0; kt < 8; kt++) {
            uint32_t a[4];
            ldsm_x4(a[0], a[1], a[2], a[3], aAddr + kt * 32);
#pragma unroll
            for (int g = 0; g < 4; g++)
                mma_f16(acc[g], a, bf[kt][g]);
        }

        float iv0 = sigm_mufu(acc[0][0] + xg_c[0].x);
        float iv1 = sigm_mufu(acc[0][1] + xg_c[0].y);
        float fv0 = sigm_mufu(acc[1][0] + xg_c[1].x);
        float fv1 = sigm_mufu(acc[1][1] + xg_c[1].y);
        float gv0 = tanh_mufu(acc[2][0] + xg_c[2].x);
        float gv1 = tanh_mufu(acc[2][1] + xg_c[2].y);
        float ov0 = sigm_mufu(acc[3][0] + xg_c[3].x);
        float ov1 = sigm_mufu(acc[3][1] + xg_c[3].y);
        cc0 = fv0 * cc0 + iv0 * gv0;
        cc1 = fv1 * cc1 + iv1 * gv1;
        float h0 = ov0 * tanh_mufu(cc0);
        float h1 = ov1 * tanh_mufu(cc1);

        __half* hw = p ? hb0 : hb1;
        *(__half2*)&hw[gid * HB_STRIDE + col0] = __floats2half2_rn(h0, h1);
        *(float2*)&hsrow[step * Dd] = make_float2(to_tf32(h0), to_tf32(h1));
        __syncthreads();
        p ^= 1;
#pragma unroll
        for (int g = 0; g < 4; g++) xg_c[g] = xg_n[g];
    }
}

// ---------------- 4) MHA core: register-cached q, float4/broadcast LDS ------
// One block per (b, head). qs/ks/vs stored with stride 36 (16B-aligned pad).
// Scores: thread (r = t>>1, half = t&1) keeps q[r] in 8 float4 regs; ks[c]
// loads are 2-address warp broadcasts. AV: thread (s, e-quad); vs[c] row read
// as conflict-free float4, sc[s][c] broadcast.
#define QK_STRIDE 36
__global__ __launch_bounds__(128) void mha_kernel() {
    int bh = blockIdx.x;
    int b = bh >> 2, h = bh & 3;
    __shared__ float qs[Ss][QK_STRIDE], ks[Ss][QK_STRIDE], vs[Ss][QK_STRIDE];
    __shared__ float sc[Ss][52];
    int t = threadIdx.x;

    // load q|k|v as float4 (1200 quads)
    for (int idx = t; idx < 3 * Ss * 8; idx += 128) {
        int which = idx / (Ss * 8);
        int rem = idx - which * (Ss * 8);
        int s = rem >> 3, q4 = rem & 7;
        float4 v = *(const float4*)&g_qkv[(b * Ss + s) * 384 + which * 128 + h * Ee + q4 * 4];
        float* dst = (which == 0) ? &qs[s][q4 * 4]
                   : (which == 1) ? &ks[s][q4 * 4] : &vs[s][q4 * 4];
        *(float4*)dst = v;
    }
    __syncthreads();

    const float scale = 0.17677669529663687f;  // 1/sqrt(32)
    // ---- scores ----
    if (t < 100) {
        int r = t >> 1;
        int c0 = (t & 1) * 25;
        float4 q[8];
#pragma unroll
        for (int i = 0; i < 8; i++) q[i] = *(float4*)&qs[r][i * 4];
        for (int c = c0; c < c0 + 25; c++) {
            float a = 0.f;
#pragma unroll
            for (int i = 0; i < 8; i++) {
                float4 k4 = *(float4*)&ks[c][i * 4];
                a += q[i].x * k4.x + q[i].y * k4.y + q[i].z * k4.z + q[i].w * k4.w;
            }
            sc[r][c] = a * scale;
        }
    }
    __syncthreads();
    // ---- softmax (row-parallel) ----
    if (t < Ss) {
        float mx = -3.4e38f;
        for (int c = 0; c < Ss; c++) mx = fmaxf(mx, sc[t][c]);
        float sm = 0.f;
        for (int c = 0; c < Ss; c++) { float e = __expf(sc[t][c] - mx); sc[t][c] = e; sm += e; }
        float inv = 1.f / sm;
        for (int c = 0; c < Ss; c++) sc[t][c] *= inv;
    }
    __syncthreads();
    // ---- AV ----
    int q4 = t & 7;
    for (int s = t >> 3; s < Ss; s += 16) {
        float4 acc = make_float4(0.f, 0.f, 0.f, 0.f);
        for (int c = 0; c < Ss; c++) {
            float a = sc[s][c];
            float4 v4 = *(float4*)&vs[c][q4 * 4];
            acc.x += a * v4.x; acc.y += a * v4.y;
            acc.z += a * v4.z; acc.w += a * v4.w;
        }
        float4 o = make_float4(to_tf32(acc.x), to_tf32(acc.y),
                               to_tf32(acc.z), to_tf32(acc.w));
        *(float4*)&g_att[(b * Ss + s) * Dd + h * Ee + q4 * 4] = o;
    }
}

// ---------------- 5) short-term attention pooling (parallel softmax) --------
__global__ __launch_bounds__(128) void shortpool_kernel() {
    int b = blockIdx.x;
    __shared__ float qv[Dd];
    __shared__ float sc[64];
    __shared__ float red4[4];
    int t = threadIdx.x;
    qv[t] = g_qvec[b * Dd + t];
    if (t >= Ss && t < 64) sc[t] = -3.4e38f;
    __syncthreads();
    if (t < Ss) {
        const float* row = &g_stm[(b * Ss + t) * Dd];
        float a = 0.f;
        for (int k = 0; k < Dd; k++) a += row[k] * qv[k];
        sc[t] = a;
    }
    __syncthreads();
    if (t < 64) {
        float v = sc[t];
#pragma unroll
        for (int ofs = 16; ofs >= 1; ofs >>= 1)
            v = fmaxf(v, __shfl_xor_sync(0xFFFFFFFFu, v, ofs));
        if ((t & 31) == 0) red4[t >> 5] = v;
    }
    __syncthreads();
    float mx = fmaxf(red4[0], red4[1]);
    float ev = (t < Ss) ? __expf(sc[t] - mx) : 0.f;
    if (t < 64) sc[t] = ev;
    __syncthreads();
    if (t < 64) {
        float v = sc[t];
#pragma unroll
        for (int ofs = 16; ofs >= 1; ofs >>= 1)
            v += __shfl_xor_sync(0xFFFFFFFFu, v, ofs);
        if ((t & 31) == 0) red4[2 + (t >> 5)] = v;
    }
    __syncthreads();
    float inv = 1.f / (red4[2] + red4[3]);
    float a = 0.f;
    for (int s = 0; s < Ss; s++) a += sc[s] * g_stm[(b * Ss + s) * Dd + t];
    g_short[b * Dd + t] = a * inv;
}

// ---------------- 6) long-term field attention (float4, dedup mask) ---------
#define LT_STRIDE 36
__global__ __launch_bounds__(256) void longterm_kernel(const int* __restrict__ ltb,
                                                       const float* __restrict__ emb,
                                                       const float* __restrict__ Wt,
                                                       const float* __restrict__ bt) {
    int bi = blockIdx.x;
    int b = bi >> 2, fi = bi & 3;
    __shared__ int   ids[Ll];
    __shared__ float vecs[Ll][LT_STRIDE];
    __shared__ float sc[Ll];
    __shared__ float uv[Ee];
    __shared__ float part[8][Ee];
    __shared__ float red[256];
    int t = threadIdx.x;
    if (t < Ll) ids[t] = ltb[(b * Ll + t) * Ff + fi];
    __syncthreads();
    for (int idx = t; idx < Ll * 8; idx += 256) {           // float4 gather
        int l = idx >> 3, q4 = idx & 7;
        *(float4*)&vecs[l][q4 * 4] = *(const float4*)&emb[ids[l] * Ee + q4 * 4];
    }
    {
        int e = t & 31, g = t >> 5;
        float a = 0.f;
        for (int k = g * 32; k < g * 32 + 32; k++)
            a += g_user_e[b * UE + k] * Wt[(fi * UE + k) * Ee + e];
        part[g][e] = a;
    }
    __syncthreads();
    if (t < Ee) {
        float a = bt[fi * Ee + t];
        for (int g = 0; g < 8; g++) a += part[g][t];
        uv[t] = a;
    }
    __syncthreads();
    if (t < Ll) {
        int mid = ids[t];
        bool keep = true;
        for (int j = 0; j < t; j++) if (ids[j] == mid) { keep = false; break; }
        float a = 0.f;
#pragma unroll
        for (int i = 0; i < 8; i++) {
            float4 v4 = *(float4*)&vecs[t][i * 4];
            float4 u4 = *(float4*)&uv[i * 4];
            a += v4.x * u4.x + v4.y * u4.y + v4.z * u4.z + v4.w * u4.w;
        }
        sc[t] = keep ? a : NEGV;
    }
    __syncthreads();
    red[t] = (t < Ll) ? sc[t] : -3.4e38f;
    __syncthreads();
    for (int ofs = 128; ofs >= 1; ofs >>= 1) {
        if (t < ofs) red[t] = fmaxf(red[t], red[t + ofs]);
        __syncthreads();
    }
    float mx = red[0];
    __syncthreads();
    float ev = (t < Ll) ? __expf(sc[t] - mx) : 0.f;
    if (t < Ll) sc[t] = ev;
    red[t] = ev;
    __syncthreads();
    for (int ofs = 128; ofs >= 1; ofs >>= 1) {
        if (t < ofs) red[t] += red[t + ofs];
        __syncthreads();
    }
    float inv = 1.f / red[0];
    __syncthreads();
    {
        int e = t & 31, g = t >> 5;
        float a = 0.f;
        for (int l = g; l < Ll; l += 8) a += sc[l] * vecs[l][e];
        part[g][e] = a;
    }
    __syncthreads();
    if (t < Ee) {
        float a = 0.f;
        for (int g = 0; g < 8; g++) a += part[g][t];
        g_long[b * Dd + fi * Ee + t] = a * inv;
    }
}

// ---------------- 7) final gate + mix ---------------------------------------
__global__ __launch_bounds__(128) void gate_kernel(
    const float* __restrict__ Wu, const float* __restrict__ bu,
    const float* __restrict__ Wsg, const float* __restrict__ bsg,
    const float* __restrict__ Wl, const float* __restrict__ bl,
    float* __restrict__ out) {
    int b = blockIdx.x, d = threadIdx.x;
    __shared__ float ue[UE], sh[Dd], lg[Dd];
    ue[d] = g_user_e[b * UE + d];
    ue[d + 128] = g_user_e[b * UE + 128 + d];
    sh[d] = g_short[b * Dd + d];
    lg[d] = g_long[b * Dd + d];
    __syncthreads();
    float a = bu[d] + bsg[d] + bl[d];
    for (int k = 0; k < UE; k++) a += ue[k] * Wu[k * Dd + d];
    for (int k = 0; k < Dd; k++) a += sh[k] * Wsg[k * Dd + d] + lg[k] * Wl[k * Dd + d];
    float g = sigm(a);
    out[b * Dd + d] = (1.f - g) * lg[d] + g * sh[d];
}

// ---------------- host ------------------------------------------------------
static float* sym(const void* s) {
    void* p = nullptr;
    cudaGetSymbolAddress(&p, s);
    return (float*)p;
}

extern "C" void kernel_launch(void* const* d_in, const int* in_sizes, int n_in,
                              void* d_out, int out_size) {
    const int*   up     = (const int*)d_in[0];
    const int*   stb    = (const int*)d_in[1];
    const int*   ltb    = (const int*)d_in[2];
    const float* emb    = (const float*)d_in[3];
    const float* lstm_W = (const float*)d_in[4];
    const float* lstm_U = (const float*)d_in[5];
    const float* lstm_b = (const float*)d_in[6];
    const float* Wq     = (const float*)d_in[7];
    const float* Wk     = (const float*)d_in[8];
    const float* Wv     = (const float*)d_in[9];
    const float* Wo     = (const float*)d_in[10];
    const float* W1     = (const float*)d_in[11];
    const float* b1     = (const float*)d_in[12];
    const float* Wt     = (const float*)d_in[13];
    const float* bt     = (const float*)d_in[14];
    const float* Wu     = (const float*)d_in[15];
    const float* bu     = (const float*)d_in[16];
    const float* Wsg    = (const float*)d_in[17];
    const float* bsg    = (const float*)d_in[18];
    const float* Wl     = (const float*)d_in[19];
    const float* bl     = (const float*)d_in[20];
    float* out = (float*)d_out;

    float* p_user  = sym(g_user_e);
    float* p_usert = sym(g_user_t);
    float* p_stx   = sym(g_stx);
    float* p_xW    = sym(g_xW);
    float* p_hs    = sym(g_hs);
    float* p_qkv   = sym(g_qkv);
    float* p_att   = sym(g_att);
    float* p_stm   = sym(g_stm);
    float* p_qvec  = sym(g_qvec);
    float* p_Wr    = sym(g_Wr);
    float* p_Wqkv  = sym(g_Wqkv);
    float* p_Wor   = sym(g_Wor);
    float* p_W1r   = sym(g_W1r);

    const int MBS = Bb * Ss;  // 51200

    // idempotent, every call (no static guards)
    cudaFuncSetAttribute(lstm_mma_kernel,
                         cudaFuncAttributeMaxDynamicSharedMemorySize,
                         LSTM_SMEM_BYTES);

    // 1) gathers + weight repacks
    {
        int total = Bb * UE + Bb * Ss * Dd;
        gather_kernel<<<(total + 255) / 256, 256>>>(up, stb, emb);
        repackU_kernel<<<(G4 * Dd + 255) / 256, 256>>>(lstm_U);
        int wtotal = Dd * G4 + Dd * 384 + Dd * Dd + UE * Dd;
        repackW_kernel<<<(wtotal + 255) / 256, 256>>>(lstm_W, Wq, Wk, Wv, Wo, W1);
    }
    // 2) xW = stx @ lstm_W + b   (51200 x 512 x 128) tf32
    gemm_tf32<<<dim3(G4 / 128, MBS / 128), 256>>>(p_stx, p_Wr, lstm_b, p_xW, MBS, G4, Dd);
    // 3) LSTM recurrence: fp16 mma, 16 warps, reg-resident U, pipelined xW
    lstm_mma_kernel<<<Bb / LSTM_ROWS, 512, LSTM_SMEM_BYTES>>>(p_xW, p_hs);
    // 4) fused QKV projection (51200 x 384 x 128) tf32
    gemm_tf32<<<dim3(384 / 128, MBS / 128), 256>>>(p_hs, p_Wqkv, nullptr, p_qkv, MBS, 384, Dd);
    // 5) attention core + output projection
    mha_kernel<<<Bb * Ff, 128>>>();
    gemm_tf32<<<dim3(Dd / 128, MBS / 128), 256>>>(p_att, p_Wor, nullptr, p_stm, MBS, Dd, Dd);
    // 6) pooling query (tf32) + short-term pooling
    gemm_tf32<<<dim3(Dd / 128, Bb / 128), 256>>>(p_usert, p_W1r, b1, p_qvec, Bb, Dd, UE);
    shortpool_kernel<<<Bb, 128>>>();
    // 7) long-term field attention
    longterm_kernel<<<Bb * Ff, 256>>>(ltb, emb, Wt, bt);
    // 8) gate + mix -> out
    gate_kernel<<<Bb, 128>>>(Wu, bu, Wsg, bsg, Wl, bl, out);
}

// round 13
// speedup vs baseline: 1.7231x; 1.0182x over previous
#include <cuda_runtime.h>
#include <cuda_fp16.h>
#include <math.h>
#include <stdint.h>

// Problem constants
#define Bb   1024
#define Uu   8
#define Ss   50
#define Ll   200
#define Ff   4
#define Ee   32
#define Dd   128      // F*E
#define UE   256      // U*E
#define G4   512      // 4*D
#define NEGV -1000000000.0f

// ---------------- scratch (static device globals) ---------------------------
__device__ float  g_user_e[Bb * UE];          // (B,256) fp32
__device__ float  g_gateA [Bb * G4];          // [user_t(256) | short_t(128) | long_t(128)] tf32
__device__ float  g_stx   [Bb * Ss * Dd];     // (B,50,128) tf32-rounded
__device__ float  g_xW    [Bb * Ss * G4];     // (B,50,512) x@W+b (fp32)
__device__ float  g_hs    [Bb * Ss * Dd];     // LSTM outputs (tf32-rounded)
__device__ float  g_qkv   [Bb * Ss * 384];    // fused q|k|v
__device__ float  g_att   [Bb * Ss * Dd];     // attn out, pre-Wo (tf32-rounded)
__device__ float  g_stm   [Bb * Ss * Dd];     // MHA out (post-Wo)
__device__ float  g_qvec  [Bb * Dd];
__device__ float  g_short [Bb * Dd];
__device__ float  g_long  [Bb * Dd];
__device__ float  g_gz    [Bb * Dd];          // gate preact
__device__ __half g_Uh    [G4 * Dd];          // U^T as fp16: [n=512][k=128]
__device__ float  g_Wr    [Dd * G4];          // tf32 lstm_W
__device__ float  g_Wqkv  [Dd * 384];         // tf32 packed Wq|Wk|Wv
__device__ float  g_Wor   [Dd * Dd];          // tf32 Wo
__device__ float  g_W1r   [UE * Dd];          // tf32 W1
__device__ float  g_Wg    [G4 * Dd];          // tf32 packed [Wu;Wsg;Wl]
__device__ float  g_bg    [Dd];               // bu+bsg+bl

__device__ __forceinline__ float sigm(float x) { return 1.0f / (1.0f + __expf(-x)); }

__device__ __forceinline__ float tanh_mufu(float x) {
    float y;
    asm("tanh.approx.f32 %0, %1;" : "=f"(y) : "f"(x));
    return y;
}
__device__ __forceinline__ float sigm_mufu(float x) {
    return fmaf(0.5f, tanh_mufu(0.5f * x), 0.5f);
}

__device__ __forceinline__ float to_tf32(float x) {
    uint32_t u;
    asm("cvt.rna.tf32.f32 %0, %1;" : "=r"(u) : "f"(x));
    return __uint_as_float(u);
}

__device__ __forceinline__ void cp16(void* smem, const void* g) {
    uint32_t s = (uint32_t)__cvta_generic_to_shared(smem);
    asm volatile("cp.async.ca.shared.global [%0], [%1], 16;" :: "r"(s), "l"(g));
}

__device__ __forceinline__ void mma_tf32(float* c, const uint32_t* a, const uint32_t* b) {
    asm volatile(
        "mma.sync.aligned.m16n8k8.row.col.f32.tf32.tf32.f32 "
        "{%0,%1,%2,%3}, {%4,%5,%6,%7}, {%8,%9}, {%0,%1,%2,%3};"
        : "+f"(c[0]), "+f"(c[1]), "+f"(c[2]), "+f"(c[3])
        : "r"(a[0]), "r"(a[1]), "r"(a[2]), "r"(a[3]), "r"(b[0]), "r"(b[1]));
}

__device__ __forceinline__ void mma_f16(float* c, const uint32_t* a, const uint32_t* b) {
    asm volatile(
        "mma.sync.aligned.m16n8k16.row.col.f32.f16.f16.f32 "
        "{%0,%1,%2,%3}, {%4,%5,%6,%7}, {%8,%9}, {%0,%1,%2,%3};"
        : "+f"(c[0]), "+f"(c[1]), "+f"(c[2]), "+f"(c[3])
        : "r"(a[0]), "r"(a[1]), "r"(a[2]), "r"(a[3]), "r"(b[0]), "r"(b[1]));
}

__device__ __forceinline__ void ldsm_x4(uint32_t& r0, uint32_t& r1, uint32_t& r2,
                                        uint32_t& r3, uint32_t addr) {
    asm volatile("ldmatrix.sync.aligned.m8n8.x4.shared.b16 {%0,%1,%2,%3}, [%4];"
                 : "=r"(r0), "=r"(r1), "=r"(r2), "=r"(r3) : "r"(addr));
}

__device__ __forceinline__ void ldsm_x2(uint32_t& r0, uint32_t& r1, uint32_t addr) {
    asm volatile("ldmatrix.sync.aligned.m8n8.x2.shared.b16 {%0,%1}, [%2];"
                 : "=r"(r0), "=r"(r1) : "r"(addr));
}

// ---------------- 1) embedding gathers --------------------------------------
__global__ void gather_kernel(const int* __restrict__ up, const int* __restrict__ stb,
                              const float* __restrict__ emb) {
    int idx = blockIdx.x * blockDim.x + threadIdx.x;
    const int n1 = Bb * UE;
    if (idx < n1) {
        int b = idx / UE, r = idx % UE;
        int u = r / Ee, e = r % Ee;
        float v = emb[up[b * Uu + u] * Ee + e];
        g_user_e[idx] = v;
        g_gateA[b * G4 + r] = to_tf32(v);
    }
    int idx2 = idx - n1;
    if (idx2 >= 0 && idx2 < Bb * Ss * Dd) {
        int e = idx2 & (Ee - 1);
        int t = idx2 / Ee;            // (b*S+s)*F + f
        int f = t & (Ff - 1);
        int bs = t / Ff;              // b*S+s
        g_stx[idx2] = to_tf32(emb[stb[bs * Ff + f] * Ee + e]);
    }
}

// ---------------- 2) weight repacks ----------------------------------------
__global__ void repackU_kernel(const float* __restrict__ Uw) {
    int idx = blockIdx.x * blockDim.x + threadIdx.x;   // 65536
    if (idx >= G4 * Dd) return;
    int n = idx >> 7, k = idx & 127;
    g_Uh[idx] = __float2half(Uw[k * G4 + n]);
}

__global__ void repackW_kernel(const float* __restrict__ lstm_W,
                               const float* __restrict__ Wq,
                               const float* __restrict__ Wk,
                               const float* __restrict__ Wv,
                               const float* __restrict__ Wo,
                               const float* __restrict__ W1,
                               const float* __restrict__ Wu,
                               const float* __restrict__ Wsg,
                               const float* __restrict__ Wl,
                               const float* __restrict__ bu,
                               const float* __restrict__ bsg,
                               const float* __restrict__ bl) {
    int idx = blockIdx.x * blockDim.x + threadIdx.x;
    if (idx < Dd * G4) {
        g_Wr[idx] = to_tf32(lstm_W[idx]);
        return;
    }
    int j = idx - Dd * G4;
    if (j < Dd * 384) {
        int k = j / 384, n = j % 384;
        float v = (n < 128) ? Wq[k * Dd + n]
                : (n < 256) ? Wk[k * Dd + (n - 128)]
                            : Wv[k * Dd + (n - 256)];
        g_Wqkv[j] = to_tf32(v);
        return;
    }
    j -= Dd * 384;
    if (j < Dd * Dd) { g_Wor[j] = to_tf32(Wo[j]); return; }
    j -= Dd * Dd;
    if (j < UE * Dd) { g_W1r[j] = to_tf32(W1[j]); return; }
    j -= UE * Dd;
    if (j < G4 * Dd) {
        int k = j >> 7, n = j & 127;
        float v = (k < 256) ? Wu[k * Dd + n]
                : (k < 384) ? Wsg[(k - 256) * Dd + n]
                            : Wl[(k - 384) * Dd + n];
        g_Wg[j] = to_tf32(v);
        return;
    }
    j -= G4 * Dd;
    if (j < Dd) g_bg[j] = bu[j] + bsg[j] + bl[j];
}

// ---------------- tf32 GEMM, 2-stage cp.async pipeline ----------------------
// C[M,N] = A[M,K] @ W[K,N] (+bias); A row stride = lda. Dyn smem: 2 stages of
// As[128][36] + Bs[32][136].
#define AS_STG 4608
#define BS_STG 4352
#define GEMM_SMEM_BYTES ((2 * (AS_STG + BS_STG)) * 4)

__global__ __launch_bounds__(256, 2) void gemm_tf32(
    const float* __restrict__ A, const float* __restrict__ W,
    const float* __restrict__ bias, float* __restrict__ C,
    int M, int N, int K, int lda) {
    extern __shared__ float gsm[];
    float* Asm = gsm;                    // 2 * 4608
    float* Bsm = gsm + 2 * AS_STG;       // 2 * 4352
    int tid = threadIdx.x;
    int lane = tid & 31, warp = tid >> 5;
    int wm = warp >> 1, wn = warp & 1;
    int g = lane >> 2, tig = lane & 3;
    int m0 = blockIdx.y * 128, n0 = blockIdx.x * 128;

    int ar = tid >> 1, ac4 = (tid & 1) * 4;        // for A loads: 2 quads/row? no:
    // A tile: 128 rows x 32 cols = 1024 float4; 256 thr x 4 iters
    // B tile: 32 rows x 128 cols = 1024 float4; 256 thr x 4 iters

    float c[2][8][4];
#pragma unroll
    for (int i = 0; i < 2; i++)
#pragma unroll
        for (int j = 0; j < 8; j++)
#pragma unroll
            for (int l = 0; l < 4; l++) c[i][j][l] = 0.f;

    // preload stage 0
    {
        float* As = Asm;
        float* Bs = Bsm;
#pragma unroll
        for (int i = 0; i < 4; i++) {
            int idx = tid + i * 256;
            int r = idx >> 3, c4 = (idx & 7) * 4;
            cp16(&As[r * 36 + c4], &A[(m0 + r) * lda + c4]);
        }
#pragma unroll
        for (int i = 0; i < 4; i++) {
            int idx = tid + i * 256;
            int r = idx >> 5, c4 = (idx & 31) * 4;
            cp16(&Bs[r * 136 + c4], &W[r * N + n0 + c4]);
        }
        asm volatile("cp.async.commit_group;");
    }

    int cur = 0;
    for (int k0 = 0; k0 < K; k0 += 32) {
        if (k0 > 0) __syncthreads();               // prev compute done before overwrite
        if (k0 + 32 < K) {
            float* As = Asm + (cur ^ 1) * AS_STG;
            float* Bs = Bsm + (cur ^ 1) * BS_STG;
#pragma unroll
            for (int i = 0; i < 4; i++) {
                int idx = tid + i * 256;
                int r = idx >> 3, c4 = (idx & 7) * 4;
                cp16(&As[r * 36 + c4], &A[(m0 + r) * lda + k0 + 32 + c4]);
            }
#pragma unroll
            for (int i = 0; i < 4; i++) {
                int idx = tid + i * 256;
                int r = idx >> 5, c4 = (idx & 31) * 4;
                cp16(&Bs[r * 136 + c4], &W[(k0 + 32 + r) * N + n0 + c4]);
            }
            asm volatile("cp.async.commit_group;");
            asm volatile("cp.async.wait_group 1;");
        } else {
            asm volatile("cp.async.wait_group 0;");
        }
        __syncthreads();

        float* As = Asm + cur * AS_STG;
        float* Bs = Bsm + cur * BS_STG;
#pragma unroll
        for (int kk = 0; kk < 32; kk += 8) {
            uint32_t a[2][4], b[8][2];
#pragma unroll
            for (int mt = 0; mt < 2; mt++) {
                int mr = wm * 32 + mt * 16;
                a[mt][0] = __float_as_uint(As[(mr + g) * 36 + kk + tig]);
                a[mt][1] = __float_as_uint(As[(mr + g + 8) * 36 + kk + tig]);
                a[mt][2] = __float_as_uint(As[(mr + g) * 36 + kk + tig + 4]);
                a[mt][3] = __float_as_uint(As[(mr + g + 8) * 36 + kk + tig + 4]);
            }
#pragma unroll
            for (int nt = 0; nt < 8; nt++) {
                int nc = wn * 64 + nt * 8 + g;
                b[nt][0] = __float_as_uint(Bs[(kk + tig) * 136 + nc]);
                b[nt][1] = __float_as_uint(Bs[(kk + tig + 4) * 136 + nc]);
            }
#pragma unroll
            for (int mt = 0; mt < 2; mt++)
#pragma unroll
                for (int nt = 0; nt < 8; nt++)
                    mma_tf32(c[mt][nt], a[mt], b[nt]);
        }
        cur ^= 1;
    }

#pragma unroll
    for (int mt = 0; mt < 2; mt++) {
        int row = m0 + wm * 32 + mt * 16 + g;
#pragma unroll
        for (int nt = 0; nt < 8; nt++) {
            int col = n0 + wn * 64 + nt * 8 + 2 * tig;
            float bx = 0.f, by = 0.f;
            if (bias) { bx = bias[col]; by = bias[col + 1]; }
            float2 o0 = make_float2(c[mt][nt][0] + bx, c[mt][nt][1] + by);
            float2 o1 = make_float2(c[mt][nt][2] + bx, c[mt][nt][3] + by);
            *(float2*)&C[row * N + col] = o0;
            *(float2*)&C[(row + 8) * N + col] = o1;
        }
    }
}

// ---------------- 3) LSTM: fp16 mma, 16 warps (unchanged from best) ---------
#define UT_STRIDE 136
#define HB_STRIDE 136
#define LSTM_ROWS 8
#define LSTM_SMEM_BYTES (G4 * UT_STRIDE * 2 + 2 * 16 * HB_STRIDE * 2)

__global__ __launch_bounds__(512, 1) void lstm_mma_kernel(
    const float* __restrict__ xW, float* __restrict__ hs) {
    extern __shared__ __align__(16) char smem_raw[];
    __half* Ut  = (__half*)smem_raw;                          // [512][136]
    __half* hb0 = (__half*)(smem_raw + G4 * UT_STRIDE * 2);   // [16][136]
    __half* hb1 = hb0 + 16 * HB_STRIDE;                       // [16][136]

    int tid = threadIdx.x;
    int lane = tid & 31, warp = tid >> 5;
    int b0 = blockIdx.x * LSTM_ROWS;

    for (int i = tid; i < G4 * Dd / 8; i += 512) {
        int n = i >> 4, c = (i & 15) * 8;
        cp16(&Ut[n * UT_STRIDE + c], &g_Uh[n * Dd + c]);
    }
    for (int i = tid; i < 2 * 16 * HB_STRIDE; i += 512) hb0[i] = __float2half(0.f);
    asm volatile("cp.async.commit_group;");
    asm volatile("cp.async.wait_group 0;");
    __syncthreads();

    int arow = lane & 15;
    int akofs = (lane >> 4) * 8;
    uint32_t aAddr0 = (uint32_t)__cvta_generic_to_shared(hb0) +
                      (arow * HB_STRIDE + akofs) * 2;
    uint32_t aAddr1 = (uint32_t)__cvta_generic_to_shared(hb1) +
                      (arow * HB_STRIDE + akofs) * 2;

    uint32_t ut_base = (uint32_t)__cvta_generic_to_shared(Ut);
    int bn = lane & 7;
    int bkofs = ((lane >> 3) & 1) * 8;
    uint32_t bf[8][4][2];
#pragma unroll
    for (int g = 0; g < 4; g++) {
        uint32_t base = ut_base +
            ((g * 128 + warp * 8 + bn) * UT_STRIDE + bkofs) * 2;
#pragma unroll
        for (int kt = 0; kt < 8; kt++)
            ldsm_x2(bf[kt][g][0], bf[kt][g][1], base + kt * 32);
    }

    int gid = lane >> 2, tig = lane & 3;
    int col0 = warp * 8 + 2 * tig;
    const float* xrow = xW + (size_t)((b0 + gid) * Ss) * G4 + col0;
    float* hsrow = hs + (size_t)((b0 + gid) * Ss) * Dd + col0;

    float cc0 = 0.f, cc1 = 0.f;
    float2 xg_c[4], xg_n[4];
#pragma unroll
    for (int g = 0; g < 4; g++) {
        xg_c[g] = *(const float2*)&xrow[g * 128];
        xg_n[g] = xg_c[g];
    }

    int p = 0;
    for (int step = 0; step < Ss; step++) {
        if (step + 1 < Ss) {
            const float* xb = xrow + (step + 1) * G4;
#pragma unroll
            for (int g = 0; g < 4; g++)
                xg_n[g] = *(const float2*)&xb[g * 128];
        }

        float acc[4][4];
#pragma unroll
        for (int g = 0; g < 4; g++)
#pragma unroll
            for (int j = 0; j < 4; j++) acc[g][j] = 0.f;
        uint32_t aAddr = p ? aAddr1 : aAddr0;
#pragma unroll
        for (int kt = 0; kt < 8; kt++) {
            uint32_t a[4];
            ldsm_x4(a[0], a[1], a[2], a[3], aAddr + kt * 32);
#pragma unroll
            for (int g = 0; g < 4; g++)
                mma_f16(acc[g], a, bf[kt][g]);
        }

        float iv0 = sigm_mufu(acc[0][0] + xg_c[0].x);
        float iv1 = sigm_mufu(acc[0][1] + xg_c[0].y);
        float fv0 = sigm_mufu(acc[1][0] + xg_c[1].x);
        float fv1 = sigm_mufu(acc[1][1] + xg_c[1].y);
        float gv0 = tanh_mufu(acc[2][0] + xg_c[2].x);
        float gv1 = tanh_mufu(acc[2][1] + xg_c[2].y);
        float ov0 = sigm_mufu(acc[3][0] + xg_c[3].x);
        float ov1 = sigm_mufu(acc[3][1] + xg_c[3].y);
        cc0 = fv0 * cc0 + iv0 * gv0;
        cc1 = fv1 * cc1 + iv1 * gv1;
        float h0 = ov0 * tanh_mufu(cc0);
        float h1 = ov1 * tanh_mufu(cc1);

        __half* hw = p ? hb0 : hb1;
        *(__half2*)&hw[gid * HB_STRIDE + col0] = __floats2half2_rn(h0, h1);
        *(float2*)&hsrow[step * Dd] = make_float2(to_tf32(h0), to_tf32(h1));
        __syncthreads();
        p ^= 1;
#pragma unroll
        for (int g = 0; g < 4; g++) xg_c[g] = xg_n[g];
    }
}

// ---------------- 4) MHA core (unchanged from R12) --------------------------
#define QK_STRIDE 36
__global__ __launch_bounds__(128) void mha_kernel() {
    int bh = blockIdx.x;
    int b = bh >> 2, h = bh & 3;
    __shared__ float qs[Ss][QK_STRIDE], ks[Ss][QK_STRIDE], vs[Ss][QK_STRIDE];
    __shared__ float sc[Ss][52];
    int t = threadIdx.x;

    for (int idx = t; idx < 3 * Ss * 8; idx += 128) {
        int which = idx / (Ss * 8);
        int rem = idx - which * (Ss * 8);
        int s = rem >> 3, q4 = rem & 7;
        float4 v = *(const float4*)&g_qkv[(b * Ss + s) * 384 + which * 128 + h * Ee + q4 * 4];
        float* dst = (which == 0) ? &qs[s][q4 * 4]
                   : (which == 1) ? &ks[s][q4 * 4] : &vs[s][q4 * 4];
        *(float4*)dst = v;
    }
    __syncthreads();

    const float scale = 0.17677669529663687f;
    if (t < 100) {
        int r = t >> 1;
        int c0 = (t & 1) * 25;
        float4 q[8];
#pragma unroll
        for (int i = 0; i < 8; i++) q[i] = *(float4*)&qs[r][i * 4];
        for (int c = c0; c < c0 + 25; c++) {
            float a = 0.f;
#pragma unroll
            for (int i = 0; i < 8; i++) {
                float4 k4 = *(float4*)&ks[c][i * 4];
                a += q[i].x * k4.x + q[i].y * k4.y + q[i].z * k4.z + q[i].w * k4.w;
            }
            sc[r][c] = a * scale;
        }
    }
    __syncthreads();
    if (t < Ss) {
        float mx = -3.4e38f;
        for (int c = 0; c < Ss; c++) mx = fmaxf(mx, sc[t][c]);
        float sm = 0.f;
        for (int c = 0; c < Ss; c++) { float e = __expf(sc[t][c] - mx); sc[t][c] = e; sm += e; }
        float inv = 1.f / sm;
        for (int c = 0; c < Ss; c++) sc[t][c] *= inv;
    }
    __syncthreads();
    int q4 = t & 7;
    for (int s = t >> 3; s < Ss; s += 16) {
        float4 acc = make_float4(0.f, 0.f, 0.f, 0.f);
        for (int c = 0; c < Ss; c++) {
            float a = sc[s][c];
            float4 v4 = *(float4*)&vs[c][q4 * 4];
            acc.x += a * v4.x; acc.y += a * v4.y;
            acc.z += a * v4.z; acc.w += a * v4.w;
        }
        float4 o = make_float4(to_tf32(acc.x), to_tf32(acc.y),
                               to_tf32(acc.z), to_tf32(acc.w));
        *(float4*)&g_att[(b * Ss + s) * Dd + h * Ee + q4 * 4] = o;
    }
}

// ---------------- 5) short-term pooling (writes fp32 + tf32 gateA) ----------
__global__ __launch_bounds__(128) void shortpool_kernel() {
    int b = blockIdx.x;
    __shared__ float qv[Dd];
    __shared__ float sc[64];
    __shared__ float red4[4];
    int t = threadIdx.x;
    qv[t] = g_qvec[b * Dd + t];
    if (t >= Ss && t < 64) sc[t] = -3.4e38f;
    __syncthreads();
    if (t < Ss) {
        const float* row = &g_stm[(b * Ss + t) * Dd];
        float a = 0.f;
        for (int k = 0; k < Dd; k++) a += row[k] * qv[k];
        sc[t] = a;
    }
    __syncthreads();
    if (t < 64) {
        float v = sc[t];
#pragma unroll
        for (int ofs = 16; ofs >= 1; ofs >>= 1)
            v = fmaxf(v, __shfl_xor_sync(0xFFFFFFFFu, v, ofs));
        if ((t & 31) == 0) red4[t >> 5] = v;
    }
    __syncthreads();
    float mx = fmaxf(red4[0], red4[1]);
    float ev = (t < Ss) ? __expf(sc[t] - mx) : 0.f;
    if (t < 64) sc[t] = ev;
    __syncthreads();
    if (t < 64) {
        float v = sc[t];
#pragma unroll
        for (int ofs = 16; ofs >= 1; ofs >>= 1)
            v += __shfl_xor_sync(0xFFFFFFFFu, v, ofs);
        if ((t & 31) == 0) red4[2 + (t >> 5)] = v;
    }
    __syncthreads();
    float inv = 1.f / (red4[2] + red4[3]);
    float a = 0.f;
    for (int s = 0; s < Ss; s++) a += sc[s] * g_stm[(b * Ss + s) * Dd + t];
    float r = a * inv;
    g_short[b * Dd + t] = r;
    g_gateA[b * G4 + 256 + t] = to_tf32(r);
}

// ---------------- 6) long-term field attention (writes fp32 + tf32 gateA) ---
#define LT_STRIDE 36
__global__ __launch_bounds__(256) void longterm_kernel(const int* __restrict__ ltb,
                                                       const float* __restrict__ emb,
                                                       const float* __restrict__ Wt,
                                                       const float* __restrict__ bt) {
    int bi = blockIdx.x;
    int b = bi >> 2, fi = bi & 3;
    __shared__ int   ids[Ll];
    __shared__ float vecs[Ll][LT_STRIDE];
    __shared__ float sc[Ll];
    __shared__ float uv[Ee];
    __shared__ float part[8][Ee];
    __shared__ float red[256];
    int t = threadIdx.x;
    if (t < Ll) ids[t] = ltb[(b * Ll + t) * Ff + fi];
    __syncthreads();
    for (int idx = t; idx < Ll * 8; idx += 256) {
        int l = idx >> 3, q4 = idx & 7;
        *(float4*)&vecs[l][q4 * 4] = *(const float4*)&emb[ids[l] * Ee + q4 * 4];
    }
    {
        int e = t & 31, g = t >> 5;
        float a = 0.f;
        for (int k = g * 32; k < g * 32 + 32; k++)
            a += g_user_e[b * UE + k] * Wt[(fi * UE + k) * Ee + e];
        part[g][e] = a;
    }
    __syncthreads();
    if (t < Ee) {
        float a = bt[fi * Ee + t];
        for (int g = 0; g < 8; g++) a += part[g][t];
        uv[t] = a;
    }
    __syncthreads();
    if (t < Ll) {
        int mid = ids[t];
        bool keep = true;
        for (int j = 0; j < t; j++) if (ids[j] == mid) { keep = false; break; }
        float a = 0.f;
#pragma unroll
        for (int i = 0; i < 8; i++) {
            float4 v4 = *(float4*)&vecs[t][i * 4];
            float4 u4 = *(float4*)&uv[i * 4];
            a += v4.x * u4.x + v4.y * u4.y + v4.z * u4.z + v4.w * u4.w;
        }
        sc[t] = keep ? a : NEGV;
    }
    __syncthreads();
    red[t] = (t < Ll) ? sc[t] : -3.4e38f;
    __syncthreads();
    for (int ofs = 128; ofs >= 1; ofs >>= 1) {
        if (t < ofs) red[t] = fmaxf(red[t], red[t + ofs]);
        __syncthreads();
    }
    float mx = red[0];
    __syncthreads();
    float ev = (t < Ll) ? __expf(sc[t] - mx) : 0.f;
    if (t < Ll) sc[t] = ev;
    red[t] = ev;
    __syncthreads();
    for (int ofs = 128; ofs >= 1; ofs >>= 1) {
        if (t < ofs) red[t] += red[t + ofs];
        __syncthreads();
    }
    float inv = 1.f / red[0];
    __syncthreads();
    {
        int e = t & 31, g = t >> 5;
        float a = 0.f;
        for (int l = g; l < Ll; l += 8) a += sc[l] * vecs[l][e];
        part[g][e] = a;
    }
    __syncthreads();
    if (t < Ee) {
        float a = 0.f;
        for (int g = 0; g < 8; g++) a += part[g][t];
        float r = a * inv;
        g_long[b * Dd + fi * Ee + t] = r;
        g_gateA[b * G4 + 384 + fi * Ee + t] = to_tf32(r);
    }
}

// ---------------- 7) gate mix (elementwise; preact from GEMM) ---------------
__global__ __launch_bounds__(256) void gatemix_kernel(float* __restrict__ out) {
    int i = blockIdx.x * 256 + threadIdx.x;   // Bb*Dd
    float g = sigm(g_gz[i]);
    out[i] = (1.f - g) * g_long[i] + g * g_short[i];
}

// ---------------- host ------------------------------------------------------
static float* sym(const void* s) {
    void* p = nullptr;
    cudaGetSymbolAddress(&p, s);
    return (float*)p;
}

extern "C" void kernel_launch(void* const* d_in, const int* in_sizes, int n_in,
                              void* d_out, int out_size) {
    const int*   up     = (const int*)d_in[0];
    const int*   stb    = (const int*)d_in[1];
    const int*   ltb    = (const int*)d_in[2];
    const float* emb    = (const float*)d_in[3];
    const float* lstm_W = (const float*)d_in[4];
    const float* lstm_U = (const float*)d_in[5];
    const float* lstm_b = (const float*)d_in[6];
    const float* Wq     = (const float*)d_in[7];
    const float* Wk     = (const float*)d_in[8];
    const float* Wv     = (const float*)d_in[9];
    const float* Wo     = (const float*)d_in[10];
    const float* W1     = (const float*)d_in[11];
    const float* b1     = (const float*)d_in[12];
    const float* Wt     = (const float*)d_in[13];
    const float* bt     = (const float*)d_in[14];
    const float* Wu     = (const float*)d_in[15];
    const float* bu     = (const float*)d_in[16];
    const float* Wsg    = (const float*)d_in[17];
    const float* bsg    = (const float*)d_in[18];
    const float* Wl     = (const float*)d_in[19];
    const float* bl     = (const float*)d_in[20];
    float* out = (float*)d_out;

    float* p_gateA = sym(g_gateA);
    float* p_stx   = sym(g_stx);
    float* p_xW    = sym(g_xW);
    float* p_hs    = sym(g_hs);
    float* p_qkv   = sym(g_qkv);
    float* p_att   = sym(g_att);
    float* p_stm   = sym(g_stm);
    float* p_qvec  = sym(g_qvec);
    float* p_gz    = sym(g_gz);
    float* p_Wr    = sym(g_Wr);
    float* p_Wqkv  = sym(g_Wqkv);
    float* p_Wor   = sym(g_Wor);
    float* p_W1r   = sym(g_W1r);
    float* p_Wg    = sym(g_Wg);
    float* p_bg    = sym(g_bg);

    const int MBS = Bb * Ss;  // 51200

    // idempotent, every call (no static guards)
    cudaFuncSetAttribute(lstm_mma_kernel,
                         cudaFuncAttributeMaxDynamicSharedMemorySize,
                         LSTM_SMEM_BYTES);
    cudaFuncSetAttribute(gemm_tf32,
                         cudaFuncAttributeMaxDynamicSharedMemorySize,
                         GEMM_SMEM_BYTES);

    // 1) gathers + weight repacks
    {
        int total = Bb * UE + Bb * Ss * Dd;
        gather_kernel<<<(total + 255) / 256, 256>>>(up, stb, emb);
        repackU_kernel<<<(G4 * Dd + 255) / 256, 256>>>(lstm_U);
        int wtotal = Dd * G4 + Dd * 384 + Dd * Dd + UE * Dd + G4 * Dd + Dd;
        repackW_kernel<<<(wtotal + 255) / 256, 256>>>(
            lstm_W, Wq, Wk, Wv, Wo, W1, Wu, Wsg, Wl, bu, bsg, bl);
    }
    // 2) xW = stx @ lstm_W + b   (51200 x 512 x 128) tf32
    gemm_tf32<<<dim3(G4 / 128, MBS / 128), 256, GEMM_SMEM_BYTES>>>(
        p_stx, p_Wr, lstm_b, p_xW, MBS, G4, Dd, Dd);
    // 3) LSTM recurrence
    lstm_mma_kernel<<<Bb / LSTM_ROWS, 512, LSTM_SMEM_BYTES>>>(p_xW, p_hs);
    // 4) fused QKV projection
    gemm_tf32<<<dim3(384 / 128, MBS / 128), 256, GEMM_SMEM_BYTES>>>(
        p_hs, p_Wqkv, nullptr, p_qkv, MBS, 384, Dd, Dd);
    // 5) attention core + output projection
    mha_kernel<<<Bb * Ff, 128>>>();
    gemm_tf32<<<dim3(Dd / 128, MBS / 128), 256, GEMM_SMEM_BYTES>>>(
        p_att, p_Wor, nullptr, p_stm, MBS, Dd, Dd, Dd);
    // 6) pooling query (A = gateA user part, lda=512) + short-term pooling
    gemm_tf32<<<dim3(Dd / 128, Bb / 128), 256, GEMM_SMEM_BYTES>>>(
        p_gateA, p_W1r, b1, p_qvec, Bb, Dd, UE, G4);
    shortpool_kernel<<<Bb, 128>>>();
    // 7) long-term field attention
    longterm_kernel<<<Bb * Ff, 256>>>(ltb, emb, Wt, bt);
    // 8) gate preact GEMM ([user|short|long] @ [Wu;Wsg;Wl] + bg) + mix
    gemm_tf32<<<dim3(Dd / 128, Bb / 128), 256, GEMM_SMEM_BYTES>>>(
        p_gateA, p_Wg, p_bg, p_gz, Bb, Dd, G4, G4);
    gatemix_kernel<<<(Bb * Dd) / 256, 256>>>(out);
}

// round 14
// speedup vs baseline: 1.9136x; 1.1105x over previous
#include <cuda_runtime.h>
#include <cuda_fp16.h>
#include <math.h>
#include <stdint.h>

// Problem constants
#define Bb   1024
#define Uu   8
#define Ss   50
#define Ll   200
#define Ff   4
#define Ee   32
#define Dd   128      // F*E
#define UE   256      // U*E
#define G4   512      // 4*D
#define NEGV -1000000000.0f

// ---------------- scratch (static device globals) ---------------------------
__device__ float  g_user_e[Bb * UE];          // (B,256) fp32 (longterm)
__device__ __half g_gateAh[Bb * G4];          // [user|short|long] fp16 GEMM A
__device__ __half g_stxh  [Bb * Ss * Dd];     // embedded short-term fp16
__device__ float  g_xW    [Bb * Ss * G4];     // x@W+b (fp32)
__device__ __half g_hsh   [Bb * Ss * Dd];     // LSTM outputs fp16
__device__ float  g_qkv   [Bb * Ss * 384];    // fused q|k|v fp32
__device__ __half g_atth  [Bb * Ss * Dd];     // attn out fp16 (Wo input)
__device__ float  g_stm   [Bb * Ss * Dd];     // MHA out (post-Wo) fp32
__device__ float  g_qvec  [Bb * Dd];
__device__ float  g_short [Bb * Dd];
__device__ float  g_long  [Bb * Dd];
__device__ float  g_gz    [Bb * Dd];          // gate preact
__device__ __half g_Uh    [G4 * Dd];          // U^T fp16 [n=512][k=128]
__device__ __half g_Whr   [G4 * Dd];          // lstm_W^T fp16 [n=512][k=128]
__device__ __half g_Whqkv [384 * Dd];         // packed (Wq|Wk|Wv)^T [384][128]
__device__ __half g_Whor  [Dd * Dd];          // Wo^T [128][128]
__device__ __half g_Wh1   [Dd * UE];          // W1^T [128][256]
__device__ __half g_Whg   [Dd * G4];          // [Wu;Wsg;Wl]^T [128][512]
__device__ float  g_bg    [Dd];               // bu+bsg+bl

__device__ __forceinline__ float sigm(float x) { return 1.0f / (1.0f + __expf(-x)); }

__device__ __forceinline__ float tanh_mufu(float x) {
    float y;
    asm("tanh.approx.f32 %0, %1;" : "=f"(y) : "f"(x));
    return y;
}
__device__ __forceinline__ float sigm_mufu(float x) {
    return fmaf(0.5f, tanh_mufu(0.5f * x), 0.5f);
}

__device__ __forceinline__ void cp16(void* smem, const void* g) {
    uint32_t s = (uint32_t)__cvta_generic_to_shared(smem);
    asm volatile("cp.async.ca.shared.global [%0], [%1], 16;" :: "r"(s), "l"(g));
}

__device__ __forceinline__ void mma_f16(float* c, const uint32_t* a, const uint32_t* b) {
    asm volatile(
        "mma.sync.aligned.m16n8k16.row.col.f32.f16.f16.f32 "
        "{%0,%1,%2,%3}, {%4,%5,%6,%7}, {%8,%9}, {%0,%1,%2,%3};"
        : "+f"(c[0]), "+f"(c[1]), "+f"(c[2]), "+f"(c[3])
        : "r"(a[0]), "r"(a[1]), "r"(a[2]), "r"(a[3]), "r"(b[0]), "r"(b[1]));
}

__device__ __forceinline__ void ldsm_x4(uint32_t& r0, uint32_t& r1, uint32_t& r2,
                                        uint32_t& r3, uint32_t addr) {
    asm volatile("ldmatrix.sync.aligned.m8n8.x4.shared.b16 {%0,%1,%2,%3}, [%4];"
                 : "=r"(r0), "=r"(r1), "=r"(r2), "=r"(r3) : "r"(addr));
}

__device__ __forceinline__ void ldsm_x2(uint32_t& r0, uint32_t& r1, uint32_t addr) {
    asm volatile("ldmatrix.sync.aligned.m8n8.x2.shared.b16 {%0,%1}, [%2];"
                 : "=r"(r0), "=r"(r1) : "r"(addr));
}

// ---------------- 1) embedding gathers --------------------------------------
__global__ void gather_kernel(const int* __restrict__ up, const int* __restrict__ stb,
                              const float* __restrict__ emb) {
    int idx = blockIdx.x * blockDim.x + threadIdx.x;
    const int n1 = Bb * UE;
    if (idx < n1) {
        int b = idx / UE, r = idx % UE;
        int u = r / Ee, e = r % Ee;
        float v = emb[up[b * Uu + u] * Ee + e];
        g_user_e[idx] = v;
        g_gateAh[b * G4 + r] = __float2half(v);
    }
    int idx2 = idx - n1;
    if (idx2 >= 0 && idx2 < Bb * Ss * Dd) {
        int e = idx2 & (Ee - 1);
        int t = idx2 / Ee;            // (b*S+s)*F + f
        int f = t & (Ff - 1);
        int bs = t / Ff;              // b*S+s
        g_stxh[idx2] = __float2half(emb[stb[bs * Ff + f] * Ee + e]);
    }
}

// ---------------- 2) weight repacks (all fp16, [n][k] transposed) -----------
__global__ void repackU_kernel(const float* __restrict__ Uw) {
    int idx = blockIdx.x * blockDim.x + threadIdx.x;   // 65536
    if (idx >= G4 * Dd) return;
    int n = idx >> 7, k = idx & 127;
    g_Uh[idx] = __float2half(Uw[k * G4 + n]);
}

__global__ void repackW_kernel(const float* __restrict__ lstm_W,
                               const float* __restrict__ Wq,
                               const float* __restrict__ Wk,
                               const float* __restrict__ Wv,
                               const float* __restrict__ Wo,
                               const float* __restrict__ W1,
                               const float* __restrict__ Wu,
                               const float* __restrict__ Wsg,
                               const float* __restrict__ Wl,
                               const float* __restrict__ bu,
                               const float* __restrict__ bsg,
                               const float* __restrict__ bl) {
    int idx = blockIdx.x * blockDim.x + threadIdx.x;
    if (idx < G4 * Dd) {                       // lstm_W^T [512][128]
        int n = idx >> 7, k = idx & 127;
        g_Whr[idx] = __float2half(lstm_W[k * G4 + n]);
        return;
    }
    int j = idx - G4 * Dd;
    if (j < 384 * Dd) {                        // (Wq|Wk|Wv)^T [384][128]
        int n = j >> 7, k = j & 127;
        float v = (n < 128) ? Wq[k * Dd + n]
                : (n < 256) ? Wk[k * Dd + (n - 128)]
                            : Wv[k * Dd + (n - 256)];
        g_Whqkv[j] = __float2half(v);
        return;
    }
    j -= 384 * Dd;
    if (j < Dd * Dd) {                         // Wo^T [128][128]
        int n = j >> 7, k = j & 127;
        g_Whor[j] = __float2half(Wo[k * Dd + n]);
        return;
    }
    j -= Dd * Dd;
    if (j < Dd * UE) {                         // W1^T [128][256]
        int n = j >> 8, k = j & 255;
        g_Wh1[j] = __float2half(W1[k * Dd + n]);
        return;
    }
    j -= Dd * UE;
    if (j < Dd * G4) {                         // [Wu;Wsg;Wl]^T [128][512]
        int n = j >> 9, k = j & 511;
        float v = (k < 256) ? Wu[k * Dd + n]
                : (k < 384) ? Wsg[(k - 256) * Dd + n]
                            : Wl[(k - 384) * Dd + n];
        g_Whg[j] = __float2half(v);
        return;
    }
    j -= Dd * G4;
    if (j < Dd) g_bg[j] = bu[j] + bsg[j] + bl[j];
}

// ---------------- fp16 GEMM: C[M,N] = A[M,K] @ Wt[N,K]^T (+bias) ------------
// A fp16 [M,lda], Wt fp16 [N][K] (n-major). BM=BN=128, BK=32, double-buffered
// cp.async; smem rows padded to 40 halves (conflict-free ldmatrix). Output fp32.
#define SH 40
#define TILE_H (128 * SH)                     // halves per tile stage
#define GEMM_SMEM_BYTES (4 * TILE_H * 2)      // 2 stages x (A+B)

__global__ __launch_bounds__(256, 2) void gemm_f16(
    const __half* __restrict__ A, const __half* __restrict__ Wt,
    const float* __restrict__ bias, float* __restrict__ C,
    int M, int N, int K, int lda) {
    extern __shared__ __half hsm[];
    __half* Asm = hsm;                         // 2 * TILE_H
    __half* Bsm = hsm + 2 * TILE_H;            // 2 * TILE_H
    int tid = threadIdx.x;
    int lane = tid & 31, warp = tid >> 5;
    int wm = warp >> 1, wn = warp & 1;
    int gid = lane >> 2, tig = lane & 3;
    int m0 = blockIdx.y * 128, n0 = blockIdx.x * 128;

    // ldmatrix lane addressing
    int arow = lane & 15, akofs = (lane >> 4) * 8;
    int bn = lane & 7, bkofs = ((lane >> 3) & 1) * 8;

    float c[2][8][4];
#pragma unroll
    for (int i = 0; i < 2; i++)
#pragma unroll
        for (int j = 0; j < 8; j++)
#pragma unroll
            for (int l = 0; l < 4; l++) c[i][j][l] = 0.f;

    // preload stage 0 (k0 = 0)
    {
#pragma unroll
        for (int i = 0; i < 2; i++) {          // A: 512 8-half chunks
            int idx = tid + i * 256;
            int r = idx >> 2, c8 = (idx & 3) * 8;
            cp16(&Asm[r * SH + c8], &A[(size_t)(m0 + r) * lda + c8]);
        }
#pragma unroll
        for (int i = 0; i < 2; i++) {          // B: 512 chunks
            int idx = tid + i * 256;
            int r = idx >> 2, c8 = (idx & 3) * 8;
            cp16(&Bsm[r * SH + c8], &Wt[(size_t)(n0 + r) * K + c8]);
        }
        asm volatile("cp.async.commit_group;");
    }

    int cur = 0;
    for (int k0 = 0; k0 < K; k0 += 32) {
        if (k0 > 0) __syncthreads();
        if (k0 + 32 < K) {
            __half* As = Asm + (cur ^ 1) * TILE_H;
            __half* Bs = Bsm + (cur ^ 1) * TILE_H;
#pragma unroll
            for (int i = 0; i < 2; i++) {
                int idx = tid + i * 256;
                int r = idx >> 2, c8 = (idx & 3) * 8;
                cp16(&As[r * SH + c8], &A[(size_t)(m0 + r) * lda + k0 + 32 + c8]);
            }
#pragma unroll
            for (int i = 0; i < 2; i++) {
                int idx = tid + i * 256;
                int r = idx >> 2, c8 = (idx & 3) * 8;
                cp16(&Bs[r * SH + c8], &Wt[(size_t)(n0 + r) * K + k0 + 32 + c8]);
            }
            asm volatile("cp.async.commit_group;");
            asm volatile("cp.async.wait_group 1;");
        } else {
            asm volatile("cp.async.wait_group 0;");
        }
        __syncthreads();

        __half* As = Asm + cur * TILE_H;
        __half* Bs = Bsm + cur * TILE_H;
        uint32_t a_base = (uint32_t)__cvta_generic_to_shared(As);
        uint32_t b_base = (uint32_t)__cvta_generic_to_shared(Bs);
#pragma unroll
        for (int kt = 0; kt < 2; kt++) {
            uint32_t a[2][4];
#pragma unroll
            for (int mt = 0; mt < 2; mt++) {
                int mr = wm * 32 + mt * 16 + arow;
                ldsm_x4(a[mt][0], a[mt][1], a[mt][2], a[mt][3],
                        a_base + (mr * SH + kt * 16 + akofs) * 2);
            }
#pragma unroll
            for (int nt = 0; nt < 8; nt++) {
                uint32_t b[2];
                int nr = wn * 64 + nt * 8 + bn;
                ldsm_x2(b[0], b[1], b_base + (nr * SH + kt * 16 + bkofs) * 2);
#pragma unroll
                for (int mt = 0; mt < 2; mt++)
                    mma_f16(c[mt][nt], a[mt], b);
            }
        }
        cur ^= 1;
    }

#pragma unroll
    for (int mt = 0; mt < 2; mt++) {
        int row = m0 + wm * 32 + mt * 16 + gid;
#pragma unroll
        for (int nt = 0; nt < 8; nt++) {
            int col = n0 + wn * 64 + nt * 8 + 2 * tig;
            float bx = 0.f, by = 0.f;
            if (bias) { bx = bias[col]; by = bias[col + 1]; }
            float2 o0 = make_float2(c[mt][nt][0] + bx, c[mt][nt][1] + by);
            float2 o1 = make_float2(c[mt][nt][2] + bx, c[mt][nt][3] + by);
            *(float2*)&C[(size_t)row * N + col] = o0;
            *(float2*)&C[(size_t)(row + 8) * N + col] = o1;
        }
    }
}

// ---------------- 3) LSTM: fp16 mma, 16 warps (hs now fp16) -----------------
#define UT_STRIDE 136
#define HB_STRIDE 136
#define LSTM_ROWS 8
#define LSTM_SMEM_BYTES (G4 * UT_STRIDE * 2 + 2 * 16 * HB_STRIDE * 2)

__global__ __launch_bounds__(512, 1) void lstm_mma_kernel(
    const float* __restrict__ xW, __half* __restrict__ hs) {
    extern __shared__ __align__(16) char smem_raw[];
    __half* Ut  = (__half*)smem_raw;                          // [512][136]
    __half* hb0 = (__half*)(smem_raw + G4 * UT_STRIDE * 2);   // [16][136]
    __half* hb1 = hb0 + 16 * HB_STRIDE;                       // [16][136]

    int tid = threadIdx.x;
    int lane = tid & 31, warp = tid >> 5;
    int b0 = blockIdx.x * LSTM_ROWS;

    for (int i = tid; i < G4 * Dd / 8; i += 512) {
        int n = i >> 4, c = (i & 15) * 8;
        cp16(&Ut[n * UT_STRIDE + c], &g_Uh[n * Dd + c]);
    }
    for (int i = tid; i < 2 * 16 * HB_STRIDE; i += 512) hb0[i] = __float2half(0.f);
    asm volatile("cp.async.commit_group;");
    asm volatile("cp.async.wait_group 0;");
    __syncthreads();

    int arow = lane & 15;
    int akofs = (lane >> 4) * 8;
    uint32_t aAddr0 = (uint32_t)__cvta_generic_to_shared(hb0) +
                      (arow * HB_STRIDE + akofs) * 2;
    uint32_t aAddr1 = (uint32_t)__cvta_generic_to_shared(hb1) +
                      (arow * HB_STRIDE + akofs) * 2;

    uint32_t ut_base = (uint32_t)__cvta_generic_to_shared(Ut);
    int bn = lane & 7;
    int bkofs = ((lane >> 3) & 1) * 8;
    uint32_t bf[8][4][2];
#pragma unroll
    for (int g = 0; g < 4; g++) {
        uint32_t base = ut_base +
            ((g * 128 + warp * 8 + bn) * UT_STRIDE + bkofs) * 2;
#pragma unroll
        for (int kt = 0; kt < 8; kt++)
            ldsm_x2(bf[kt][g][0], bf[kt][g][1], base + kt * 32);
    }

    int gid = lane >> 2, tig = lane & 3;
    int col0 = warp * 8 + 2 * tig;
    const float* xrow = xW + (size_t)((b0 + gid) * Ss) * G4 + col0;
    __half* hsrow = hs + (size_t)((b0 + gid) * Ss) * Dd + col0;

    float cc0 = 0.f, cc1 = 0.f;
    float2 xg_c[4], xg_n[4];
#pragma unroll
    for (int g = 0; g < 4; g++) {
        xg_c[g] = *(const float2*)&xrow[g * 128];
        xg_n[g] = xg_c[g];
    }

    int p = 0;
    for (int step = 0; step < Ss; step++) {
        if (step + 1 < Ss) {
            const float* xb = xrow + (step + 1) * G4;
#pragma unroll
            for (int g = 0; g < 4; g++)
                xg_n[g] = *(const float2*)&xb[g * 128];
        }

        float acc[4][4];
#pragma unroll
        for (int g = 0; g < 4; g++)
#pragma unroll
            for (int j = 0; j < 4; j++) acc[g][j] = 0.f;
        uint32_t aAddr = p ? aAddr1 : aAddr0;
#pragma unroll
        for (int kt = 0; kt < 8; kt++) {
            uint32_t a[4];
            ldsm_x4(a[0], a[1], a[2], a[3], aAddr + kt * 32);
#pragma unroll
            for (int g = 0; g < 4; g++)
                mma_f16(acc[g], a, bf[kt][g]);
        }

        float iv0 = sigm_mufu(acc[0][0] + xg_c[0].x);
        float iv1 = sigm_mufu(acc[0][1] + xg_c[0].y);
        float fv0 = sigm_mufu(acc[1][0] + xg_c[1].x);
        float fv1 = sigm_mufu(acc[1][1] + xg_c[1].y);
        float gv0 = tanh_mufu(acc[2][0] + xg_c[2].x);
        float gv1 = tanh_mufu(acc[2][1] + xg_c[2].y);
        float ov0 = sigm_mufu(acc[3][0] + xg_c[3].x);
        float ov1 = sigm_mufu(acc[3][1] + xg_c[3].y);
        cc0 = fv0 * cc0 + iv0 * gv0;
        cc1 = fv1 * cc1 + iv1 * gv1;
        float h0 = ov0 * tanh_mufu(cc0);
        float h1 = ov1 * tanh_mufu(cc1);

        __half2 h01 = __floats2half2_rn(h0, h1);
        __half* hw = p ? hb0 : hb1;
        *(__half2*)&hw[gid * HB_STRIDE + col0] = h01;
        *(__half2*)&hsrow[step * Dd] = h01;
        __syncthreads();
        p ^= 1;
#pragma unroll
        for (int g = 0; g < 4; g++) xg_c[g] = xg_n[g];
    }
}

// ---------------- 4) MHA core (att out fp16) --------------------------------
#define QK_STRIDE 36
__global__ __launch_bounds__(128) void mha_kernel() {
    int bh = blockIdx.x;
    int b = bh >> 2, h = bh & 3;
    __shared__ float qs[Ss][QK_STRIDE], ks[Ss][QK_STRIDE], vs[Ss][QK_STRIDE];
    __shared__ float sc[Ss][52];
    int t = threadIdx.x;

    for (int idx = t; idx < 3 * Ss * 8; idx += 128) {
        int which = idx / (Ss * 8);
        int rem = idx - which * (Ss * 8);
        int s = rem >> 3, q4 = rem & 7;
        float4 v = *(const float4*)&g_qkv[(b * Ss + s) * 384 + which * 128 + h * Ee + q4 * 4];
        float* dst = (which == 0) ? &qs[s][q4 * 4]
                   : (which == 1) ? &ks[s][q4 * 4] : &vs[s][q4 * 4];
        *(float4*)dst = v;
    }
    __syncthreads();

    const float scale = 0.17677669529663687f;
    if (t < 100) {
        int r = t >> 1;
        int c0 = (t & 1) * 25;
        float4 q[8];
#pragma unroll
        for (int i = 0; i < 8; i++) q[i] = *(float4*)&qs[r][i * 4];
        for (int c = c0; c < c0 + 25; c++) {
            float a = 0.f;
#pragma unroll
            for (int i = 0; i < 8; i++) {
                float4 k4 = *(float4*)&ks[c][i * 4];
                a += q[i].x * k4.x + q[i].y * k4.y + q[i].z * k4.z + q[i].w * k4.w;
            }
            sc[r][c] = a * scale;
        }
    }
    __syncthreads();
    if (t < Ss) {
        float mx = -3.4e38f;
        for (int c = 0; c < Ss; c++) mx = fmaxf(mx, sc[t][c]);
        float sm = 0.f;
        for (int c = 0; c < Ss; c++) { float e = __expf(sc[t][c] - mx); sc[t][c] = e; sm += e; }
        float inv = 1.f / sm;
        for (int c = 0; c < Ss; c++) sc[t][c] *= inv;
    }
    __syncthreads();
    int q4 = t & 7;
    for (int s = t >> 3; s < Ss; s += 16) {
        float4 acc = make_float4(0.f, 0.f, 0.f, 0.f);
        for (int c = 0; c < Ss; c++) {
            float a = sc[s][c];
            float4 v4 = *(float4*)&vs[c][q4 * 4];
            acc.x += a * v4.x; acc.y += a * v4.y;
            acc.z += a * v4.z; acc.w += a * v4.w;
        }
        __half2 o01 = __floats2half2_rn(acc.x, acc.y);
        __half2 o23 = __floats2half2_rn(acc.z, acc.w);
        __half* dst = &g_atth[(b * Ss + s) * Dd + h * Ee + q4 * 4];
        *(__half2*)&dst[0] = o01;
        *(__half2*)&dst[2] = o23;
    }
}

// ---------------- 5) short-term pooling -------------------------------------
__global__ __launch_bounds__(128) void shortpool_kernel() {
    int b = blockIdx.x;
    __shared__ float qv[Dd];
    __shared__ float sc[64];
    __shared__ float red4[4];
    int t = threadIdx.x;
    qv[t] = g_qvec[b * Dd + t];
    if (t >= Ss && t < 64) sc[t] = -3.4e38f;
    __syncthreads();
    if (t < Ss) {
        const float* row = &g_stm[(b * Ss + t) * Dd];
        float a = 0.f;
        for (int k = 0; k < Dd; k++) a += row[k] * qv[k];
        sc[t] = a;
    }
    __syncthreads();
    if (t < 64) {
        float v = sc[t];
#pragma unroll
        for (int ofs = 16; ofs >= 1; ofs >>= 1)
            v = fmaxf(v, __shfl_xor_sync(0xFFFFFFFFu, v, ofs));
        if ((t & 31) == 0) red4[t >> 5] = v;
    }
    __syncthreads();
    float mx = fmaxf(red4[0], red4[1]);
    float ev = (t < Ss) ? __expf(sc[t] - mx) : 0.f;
    if (t < 64) sc[t] = ev;
    __syncthreads();
    if (t < 64) {
        float v = sc[t];
#pragma unroll
        for (int ofs = 16; ofs >= 1; ofs >>= 1)
            v += __shfl_xor_sync(0xFFFFFFFFu, v, ofs);
        if ((t & 31) == 0) red4[2 + (t >> 5)] = v;
    }
    __syncthreads();
    float inv = 1.f / (red4[2] + red4[3]);
    float a = 0.f;
    for (int s = 0; s < Ss; s++) a += sc[s] * g_stm[(b * Ss + s) * Dd + t];
    float r = a * inv;
    g_short[b * Dd + t] = r;
    g_gateAh[b * G4 + 256 + t] = __float2half(r);
}

// ---------------- 6) long-term field attention ------------------------------
#define LT_STRIDE 36
__global__ __launch_bounds__(256) void longterm_kernel(const int* __restrict__ ltb,
                                                       const float* __restrict__ emb,
                                                       const float* __restrict__ Wt,
                                                       const float* __restrict__ bt) {
    int bi = blockIdx.x;
    int b = bi >> 2, fi = bi & 3;
    __shared__ int   ids[Ll];
    __shared__ float vecs[Ll][LT_STRIDE];
    __shared__ float sc[Ll];
    __shared__ float uv[Ee];
    __shared__ float part[8][Ee];
    __shared__ float red[256];
    int t = threadIdx.x;
    if (t < Ll) ids[t] = ltb[(b * Ll + t) * Ff + fi];
    __syncthreads();
    for (int idx = t; idx < Ll * 8; idx += 256) {
        int l = idx >> 3, q4 = idx & 7;
        *(float4*)&vecs[l][q4 * 4] = *(const float4*)&emb[ids[l] * Ee + q4 * 4];
    }
    {
        int e = t & 31, g = t >> 5;
        float a = 0.f;
        for (int k = g * 32; k < g * 32 + 32; k++)
            a += g_user_e[b * UE + k] * Wt[(fi * UE + k) * Ee + e];
        part[g][e] = a;
    }
    __syncthreads();
    if (t < Ee) {
        float a = bt[fi * Ee + t];
        for (int g = 0; g < 8; g++) a += part[g][t];
        uv[t] = a;
    }
    __syncthreads();
    if (t < Ll) {
        int mid = ids[t];
        bool keep = true;
        for (int j = 0; j < t; j++) if (ids[j] == mid) { keep = false; break; }
        float a = 0.f;
#pragma unroll
        for (int i = 0; i < 8; i++) {
            float4 v4 = *(float4*)&vecs[t][i * 4];
            float4 u4 = *(float4*)&uv[i * 4];
            a += v4.x * u4.x + v4.y * u4.y + v4.z * u4.z + v4.w * u4.w;
        }
        sc[t] = keep ? a : NEGV;
    }
    __syncthreads();
    red[t] = (t < Ll) ? sc[t] : -3.4e38f;
    __syncthreads();
    for (int ofs = 128; ofs >= 1; ofs >>= 1) {
        if (t < ofs) red[t] = fmaxf(red[t], red[t + ofs]);
        __syncthreads();
    }
    float mx = red[0];
    __syncthreads();
    float ev = (t < Ll) ? __expf(sc[t] - mx) : 0.f;
    if (t < Ll) sc[t] = ev;
    red[t] = ev;
    __syncthreads();
    for (int ofs = 128; ofs >= 1; ofs >>= 1) {
        if (t < ofs) red[t] += red[t + ofs];
        __syncthreads();
    }
    float inv = 1.f / red[0];
    __syncthreads();
    {
        int e = t & 31, g = t >> 5;
        float a = 0.f;
        for (int l = g; l < Ll; l += 8) a += sc[l] * vecs[l][e];
        part[g][e] = a;
    }
    __syncthreads();
    if (t < Ee) {
        float a = 0.f;
        for (int g = 0; g < 8; g++) a += part[g][t];
        float r = a * inv;
        g_long[b * Dd + fi * Ee + t] = r;
        g_gateAh[b * G4 + 384 + fi * Ee + t] = __float2half(r);
    }
}

// ---------------- 7) gate mix ------------------------------------------------
__global__ __launch_bounds__(256) void gatemix_kernel(float* __restrict__ out) {
    int i = blockIdx.x * 256 + threadIdx.x;
    float g = sigm(g_gz[i]);
    out[i] = (1.f - g) * g_long[i] + g * g_short[i];
}

// ---------------- host ------------------------------------------------------
static void* symv(const void* s) {
    void* p = nullptr;
    cudaGetSymbolAddress(&p, s);
    return p;
}

extern "C" void kernel_launch(void* const* d_in, const int* in_sizes, int n_in,
                              void* d_out, int out_size) {
    const int*   up     = (const int*)d_in[0];
    const int*   stb    = (const int*)d_in[1];
    const int*   ltb    = (const int*)d_in[2];
    const float* emb    = (const float*)d_in[3];
    const float* lstm_W = (const float*)d_in[4];
    const float* lstm_U = (const float*)d_in[5];
    const float* lstm_b = (const float*)d_in[6];
    const float* Wq     = (const float*)d_in[7];
    const float* Wk     = (const float*)d_in[8];
    const float* Wv     = (const float*)d_in[9];
    const float* Wo     = (const float*)d_in[10];
    const float* W1     = (const float*)d_in[11];
    const float* b1     = (const float*)d_in[12];
    const float* Wt     = (const float*)d_in[13];
    const float* bt     = (const float*)d_in[14];
    const float* Wu     = (const float*)d_in[15];
    const float* bu     = (const float*)d_in[16];
    const float* Wsg    = (const float*)d_in[17];
    const float* bsg    = (const float*)d_in[18];
    const float* Wl     = (const float*)d_in[19];
    const float* bl     = (const float*)d_in[20];
    float* out = (float*)d_out;

    __half* p_gateAh = (__half*)symv(g_gateAh);
    __half* p_stxh   = (__half*)symv(g_stxh);
    float*  p_xW     = (float*)symv(g_xW);
    __half* p_hsh    = (__half*)symv(g_hsh);
    float*  p_qkv    = (float*)symv(g_qkv);
    __half* p_atth   = (__half*)symv(g_atth);
    float*  p_stm    = (float*)symv(g_stm);
    float*  p_qvec   = (float*)symv(g_qvec);
    float*  p_gz     = (float*)symv(g_gz);
    __half* p_Whr    = (__half*)symv(g_Whr);
    __half* p_Whqkv  = (__half*)symv(g_Whqkv);
    __half* p_Whor   = (__half*)symv(g_Whor);
    __half* p_Wh1    = (__half*)symv(g_Wh1);
    __half* p_Whg    = (__half*)symv(g_Whg);
    float*  p_bg     = (float*)symv(g_bg);

    const int MBS = Bb * Ss;  // 51200

    // idempotent, every call (no static guards)
    cudaFuncSetAttribute(lstm_mma_kernel,
                         cudaFuncAttributeMaxDynamicSharedMemorySize,
                         LSTM_SMEM_BYTES);
    cudaFuncSetAttribute(gemm_f16,
                         cudaFuncAttributeMaxDynamicSharedMemorySize,
                         GEMM_SMEM_BYTES);

    // 1) gathers + weight repacks
    {
        int total = Bb * UE + Bb * Ss * Dd;
        gather_kernel<<<(total + 255) / 256, 256>>>(up, stb, emb);
        repackU_kernel<<<(G4 * Dd + 255) / 256, 256>>>(lstm_U);
        int wtotal = G4 * Dd + 384 * Dd + Dd * Dd + Dd * UE + Dd * G4 + Dd;
        repackW_kernel<<<(wtotal + 255) / 256, 256>>>(
            lstm_W, Wq, Wk, Wv, Wo, W1, Wu, Wsg, Wl, bu, bsg, bl);
    }
    // 2) xW = stx @ lstm_W + b   (51200 x 512 x 128) fp16
    gemm_f16<<<dim3(G4 / 128, MBS / 128), 256, GEMM_SMEM_BYTES>>>(
        p_stxh, p_Whr, lstm_b, p_xW, MBS, G4, Dd, Dd);
    // 3) LSTM recurrence
    lstm_mma_kernel<<<Bb / LSTM_ROWS, 512, LSTM_SMEM_BYTES>>>(p_xW, p_hsh);
    // 4) fused QKV projection (51200 x 384 x 128) fp16
    gemm_f16<<<dim3(384 / 128, MBS / 128), 256, GEMM_SMEM_BYTES>>>(
        p_hsh, p_Whqkv, nullptr, p_qkv, MBS, 384, Dd, Dd);
    // 5) attention core + output projection
    mha_kernel<<<Bb * Ff, 128>>>();
    gemm_f16<<<dim3(Dd / 128, MBS / 128), 256, GEMM_SMEM_BYTES>>>(
        p_atth, p_Whor, nullptr, p_stm, MBS, Dd, Dd, Dd);
    // 6) pooling query + short-term pooling
    gemm_f16<<<dim3(Dd / 128, Bb / 128), 256, GEMM_SMEM_BYTES>>>(
        p_gateAh, p_Wh1, b1, p_qvec, Bb, Dd, UE, G4);
    shortpool_kernel<<<Bb, 128>>>();
    // 7) long-term field attention
    longterm_kernel<<<Bb * Ff, 256>>>(ltb, emb, Wt, bt);
    // 8) gate preact GEMM + mix
    gemm_f16<<<dim3(Dd / 128, Bb / 128), 256, GEMM_SMEM_BYTES>>>(
        p_gateAh, p_Whg, p_bg, p_gz, Bb, Dd, G4, G4);
    gatemix_kernel<<<(Bb * Dd) / 256, 256>>>(out);
}

// round 16
// speedup vs baseline: 1.9883x; 1.0390x over previous
#include <cuda_runtime.h>
#include <cuda_fp16.h>
#include <math.h>
#include <stdint.h>

// Problem constants
#define Bb   1024
#define Uu   8
#define Ss   50
#define Ll   200
#define Ff   4
#define Ee   32
#define Dd   128      // F*E
#define UE   256      // U*E
#define G4   512      // 4*D
#define NEGV -1000000000.0f

// ---------------- scratch (static device globals) ---------------------------
__device__ float  g_user_e[Bb * UE];          // (B,256) fp32 (longterm)
__device__ __half g_gateAh[Bb * G4];          // [user|short|long] fp16 GEMM A
__device__ __half g_stxh  [Bb * Ss * Dd];     // embedded short-term fp16
__device__ __half g_xWh   [Bb * Ss * G4];     // x@W+b fp16
__device__ __half g_hsh   [Bb * Ss * Dd];     // LSTM outputs fp16
__device__ __half g_qkvh  [Bb * Ss * 384];    // fused q|k|v fp16
__device__ __half g_atth  [Bb * Ss * Dd];     // attn out fp16 (Wo input)
__device__ float  g_stm   [Bb * Ss * Dd];     // MHA out (post-Wo) fp32
__device__ float  g_qvec  [Bb * Dd];
__device__ float  g_short [Bb * Dd];
__device__ float  g_long  [Bb * Dd];
__device__ float  g_gz    [Bb * Dd];          // gate preact
__device__ __half g_Uh    [G4 * Dd];          // U^T fp16 [n=512][k=128]
__device__ __half g_Whr   [G4 * Dd];          // lstm_W^T fp16 [n=512][k=128]
__device__ __half g_Whqkv [384 * Dd];         // packed (Wq|Wk|Wv)^T [384][128]
__device__ __half g_Whor  [Dd * Dd];          // Wo^T [128][128]
__device__ __half g_Wh1   [Dd * UE];          // W1^T [128][256]
__device__ __half g_Whg   [Dd * G4];          // [Wu;Wsg;Wl]^T [128][512]
__device__ float  g_bg    [Dd];               // bu+bsg+bl

__device__ __forceinline__ float sigm(float x) { return 1.0f / (1.0f + __expf(-x)); }

__device__ __forceinline__ float tanh_mufu(float x) {
    float y;
    asm("tanh.approx.f32 %0, %1;" : "=f"(y) : "f"(x));
    return y;
}
__device__ __forceinline__ float sigm_mufu(float x) {
    return fmaf(0.5f, tanh_mufu(0.5f * x), 0.5f);
}

__device__ __forceinline__ void cp16(void* smem, const void* g) {
    uint32_t s = (uint32_t)__cvta_generic_to_shared(smem);
    asm volatile("cp.async.ca.shared.global [%0], [%1], 16;" :: "r"(s), "l"(g));
}

__device__ __forceinline__ void mma_f16(float* c, const uint32_t* a, const uint32_t* b) {
    asm volatile(
        "mma.sync.aligned.m16n8k16.row.col.f32.f16.f16.f32 "
        "{%0,%1,%2,%3}, {%4,%5,%6,%7}, {%8,%9}, {%0,%1,%2,%3};"
        : "+f"(c[0]), "+f"(c[1]), "+f"(c[2]), "+f"(c[3])
        : "r"(a[0]), "r"(a[1]), "r"(a[2]), "r"(a[3]), "r"(b[0]), "r"(b[1]));
}

__device__ __forceinline__ void ldsm_x4(uint32_t& r0, uint32_t& r1, uint32_t& r2,
                                        uint32_t& r3, uint32_t addr) {
    asm volatile("ldmatrix.sync.aligned.m8n8.x4.shared.b16 {%0,%1,%2,%3}, [%4];"
                 : "=r"(r0), "=r"(r1), "=r"(r2), "=r"(r3) : "r"(addr));
}

__device__ __forceinline__ void ldsm_x2(uint32_t& r0, uint32_t& r1, uint32_t addr) {
    asm volatile("ldmatrix.sync.aligned.m8n8.x2.shared.b16 {%0,%1}, [%2];"
                 : "=r"(r0), "=r"(r1) : "r"(addr));
}

// ---------------- 1) combined prep: gathers + all weight repacks ------------
__global__ void prep_kernel(const int* __restrict__ up, const int* __restrict__ stb,
                            const float* __restrict__ emb,
                            const float* __restrict__ Uw,
                            const float* __restrict__ lstm_W,
                            const float* __restrict__ Wq,
                            const float* __restrict__ Wk,
                            const float* __restrict__ Wv,
                            const float* __restrict__ Wo,
                            const float* __restrict__ W1,
                            const float* __restrict__ Wu,
                            const float* __restrict__ Wsg,
                            const float* __restrict__ Wl,
                            const float* __restrict__ bu,
                            const float* __restrict__ bsg,
                            const float* __restrict__ bl) {
    int idx = blockIdx.x * blockDim.x + threadIdx.x;
    // stx gather (bulk, first so it launches first)
    if (idx < Bb * Ss * Dd) {
        int e = idx & (Ee - 1);
        int t = idx / Ee;
        int f = t & (Ff - 1);
        int bs = t / Ff;
        g_stxh[idx] = __float2half(emb[stb[bs * Ff + f] * Ee + e]);
        return;
    }
    int j = idx - Bb * Ss * Dd;
    if (j < Bb * UE) {
        int b = j / UE, r = j % UE;
        int u = r / Ee, e = r % Ee;
        float v = emb[up[b * Uu + u] * Ee + e];
        g_user_e[j] = v;
        g_gateAh[b * G4 + r] = __float2half(v);
        return;
    }
    j -= Bb * UE;
    if (j < G4 * Dd) {                         // U^T
        int n = j >> 7, k = j & 127;
        g_Uh[j] = __float2half(Uw[k * G4 + n]);
        return;
    }
    j -= G4 * Dd;
    if (j < G4 * Dd) {                         // lstm_W^T [512][128]
        int n = j >> 7, k = j & 127;
        g_Whr[j] = __float2half(lstm_W[k * G4 + n]);
        return;
    }
    j -= G4 * Dd;
    if (j < 384 * Dd) {                        // (Wq|Wk|Wv)^T [384][128]
        int n = j >> 7, k = j & 127;
        float v = (n < 128) ? Wq[k * Dd + n]
                : (n < 256) ? Wk[k * Dd + (n - 128)]
                            : Wv[k * Dd + (n - 256)];
        g_Whqkv[j] = __float2half(v);
        return;
    }
    j -= 384 * Dd;
    if (j < Dd * Dd) {                         // Wo^T [128][128]
        int n = j >> 7, k = j & 127;
        g_Whor[j] = __float2half(Wo[k * Dd + n]);
        return;
    }
    j -= Dd * Dd;
    if (j < Dd * UE) {                         // W1^T [128][256]
        int n = j >> 8, k = j & 255;
        g_Wh1[j] = __float2half(W1[k * Dd + n]);
        return;
    }
    j -= Dd * UE;
    if (j < Dd * G4) {                         // [Wu;Wsg;Wl]^T [128][512]
        int n = j >> 9, k = j & 511;
        float v = (k < 256) ? Wu[k * Dd + n]
                : (k < 384) ? Wsg[(k - 256) * Dd + n]
                            : Wl[(k - 384) * Dd + n];
        g_Whg[j] = __float2half(v);
        return;
    }
    j -= Dd * G4;
    if (j < Dd) g_bg[j] = bu[j] + bsg[j] + bl[j];
}

// ---------------- fp16 GEMM: C = A[M,K] @ Wt[N,K]^T (+bias) -----------------
// Output: fp32 to C if Ch==nullptr, else fp16 to Ch.
#define SH 40
#define TILE_H (128 * SH)
#define GEMM_SMEM_BYTES (4 * TILE_H * 2)

__global__ __launch_bounds__(256, 2) void gemm_f16(
    const __half* __restrict__ A, const __half* __restrict__ Wt,
    const float* __restrict__ bias, float* __restrict__ C,
    __half* __restrict__ Ch, int M, int N, int K, int lda) {
    extern __shared__ __half hsm[];
    __half* Asm = hsm;
    __half* Bsm = hsm + 2 * TILE_H;
    int tid = threadIdx.x;
    int lane = tid & 31, warp = tid >> 5;
    int wm = warp >> 1, wn = warp & 1;
    int gid = lane >> 2, tig = lane & 3;
    int m0 = blockIdx.y * 128, n0 = blockIdx.x * 128;

    int arow = lane & 15, akofs = (lane >> 4) * 8;
    int bn = lane & 7, bkofs = ((lane >> 3) & 1) * 8;

    float c[2][8][4];
#pragma unroll
    for (int i = 0; i < 2; i++)
#pragma unroll
        for (int j = 0; j < 8; j++)
#pragma unroll
            for (int l = 0; l < 4; l++) c[i][j][l] = 0.f;

    {
#pragma unroll
        for (int i = 0; i < 2; i++) {
            int idx = tid + i * 256;
            int r = idx >> 2, c8 = (idx & 3) * 8;
            cp16(&Asm[r * SH + c8], &A[(size_t)(m0 + r) * lda + c8]);
        }
#pragma unroll
        for (int i = 0; i < 2; i++) {
            int idx = tid + i * 256;
            int r = idx >> 2, c8 = (idx & 3) * 8;
            cp16(&Bsm[r * SH + c8], &Wt[(size_t)(n0 + r) * K + c8]);
        }
        asm volatile("cp.async.commit_group;");
    }

    int cur = 0;
    for (int k0 = 0; k0 < K; k0 += 32) {
        if (k0 > 0) __syncthreads();
        if (k0 + 32 < K) {
            __half* As = Asm + (cur ^ 1) * TILE_H;
            __half* Bs = Bsm + (cur ^ 1) * TILE_H;
#pragma unroll
            for (int i = 0; i < 2; i++) {
                int idx = tid + i * 256;
                int r = idx >> 2, c8 = (idx & 3) * 8;
                cp16(&As[r * SH + c8], &A[(size_t)(m0 + r) * lda + k0 + 32 + c8]);
            }
#pragma unroll
            for (int i = 0; i < 2; i++) {
                int idx = tid + i * 256;
                int r = idx >> 2, c8 = (idx & 3) * 8;
                cp16(&Bs[r * SH + c8], &Wt[(size_t)(n0 + r) * K + k0 + 32 + c8]);
            }
            asm volatile("cp.async.commit_group;");
            asm volatile("cp.async.wait_group 1;");
        } else {
            asm volatile("cp.async.wait_group 0;");
        }
        __syncthreads();

        __half* As = Asm + cur * TILE_H;
        __half* Bs = Bsm + cur * TILE_H;
        uint32_t a_base = (uint32_t)__cvta_generic_to_shared(As);
        uint32_t b_base = (uint32_t)__cvta_generic_to_shared(Bs);
#pragma unroll
        for (int kt = 0; kt < 2; kt++) {
            uint32_t a[2][4];
#pragma unroll
            for (int mt = 0; mt < 2; mt++) {
                int mr = wm * 32 + mt * 16 + arow;
                ldsm_x4(a[mt][0], a[mt][1], a[mt][2], a[mt][3],
                        a_base + (mr * SH + kt * 16 + akofs) * 2);
            }
#pragma unroll
            for (int nt = 0; nt < 8; nt++) {
                uint32_t b[2];
                int nr = wn * 64 + nt * 8 + bn;
                ldsm_x2(b[0], b[1], b_base + (nr * SH + kt * 16 + bkofs) * 2);
#pragma unroll
                for (int mt = 0; mt < 2; mt++)
                    mma_f16(c[mt][nt], a[mt], b);
            }
        }
        cur ^= 1;
    }

#pragma unroll
    for (int mt = 0; mt < 2; mt++) {
        int row = m0 + wm * 32 + mt * 16 + gid;
#pragma unroll
        for (int nt = 0; nt < 8; nt++) {
            int col = n0 + wn * 64 + nt * 8 + 2 * tig;
            float bx = 0.f, by = 0.f;
            if (bias) { bx = bias[col]; by = bias[col + 1]; }
            float v00 = c[mt][nt][0] + bx, v01 = c[mt][nt][1] + by;
            float v10 = c[mt][nt][2] + bx, v11 = c[mt][nt][3] + by;
            if (Ch) {
                *(__half2*)&Ch[(size_t)row * N + col] = __floats2half2_rn(v00, v01);
                *(__half2*)&Ch[(size_t)(row + 8) * N + col] = __floats2half2_rn(v10, v11);
            } else {
                *(float2*)&C[(size_t)row * N + col] = make_float2(v00, v01);
                *(float2*)&C[(size_t)(row + 8) * N + col] = make_float2(v10, v11);
            }
        }
    }
}

// ---------------- 3) LSTM: fp16 mma, 16 warps (xW + hs fp16) ----------------
#define UT_STRIDE 136
#define HB_STRIDE 136
#define LSTM_ROWS 8
#define LSTM_SMEM_BYTES (G4 * UT_STRIDE * 2 + 2 * 16 * HB_STRIDE * 2)

__global__ __launch_bounds__(512, 1) void lstm_mma_kernel(
    const __half* __restrict__ xW, __half* __restrict__ hs) {
    extern __shared__ __align__(16) char smem_raw[];
    __half* Ut  = (__half*)smem_raw;                          // [512][136]
    __half* hb0 = (__half*)(smem_raw + G4 * UT_STRIDE * 2);   // [16][136]
    __half* hb1 = hb0 + 16 * HB_STRIDE;                       // [16][136]

    int tid = threadIdx.x;
    int lane = tid & 31, warp = tid >> 5;
    int b0 = blockIdx.x * LSTM_ROWS;

    for (int i = tid; i < G4 * Dd / 8; i += 512) {
        int n = i >> 4, c = (i & 15) * 8;
        cp16(&Ut[n * UT_STRIDE + c], &g_Uh[n * Dd + c]);
    }
    for (int i = tid; i < 2 * 16 * HB_STRIDE; i += 512) hb0[i] = __float2half(0.f);
    asm volatile("cp.async.commit_group;");
    asm volatile("cp.async.wait_group 0;");
    __syncthreads();

    int arow = lane & 15;
    int akofs = (lane >> 4) * 8;
    uint32_t aAddr0 = (uint32_t)__cvta_generic_to_shared(hb0) +
                      (arow * HB_STRIDE + akofs) * 2;
    uint32_t aAddr1 = (uint32_t)__cvta_generic_to_shared(hb1) +
                      (arow * HB_STRIDE + akofs) * 2;

    uint32_t ut_base = (uint32_t)__cvta_generic_to_shared(Ut);
    int bn = lane & 7;
    int bkofs = ((lane >> 3) & 1) * 8;
    uint32_t bf[8][4][2];
#pragma unroll
    for (int g = 0; g < 4; g++) {
        uint32_t base = ut_base +
            ((g * 128 + warp * 8 + bn) * UT_STRIDE + bkofs) * 2;
#pragma unroll
        for (int kt = 0; kt < 8; kt++)
            ldsm_x2(bf[kt][g][0], bf[kt][g][1], base + kt * 32);
    }

    int gid = lane >> 2, tig = lane & 3;
    int col0 = warp * 8 + 2 * tig;
    const __half* xrow = xW + (size_t)((b0 + gid) * Ss) * G4 + col0;
    __half* hsrow = hs + (size_t)((b0 + gid) * Ss) * Dd + col0;

    float cc0 = 0.f, cc1 = 0.f;
    float2 xg_c[4], xg_n[4];
#pragma unroll
    for (int g = 0; g < 4; g++) {
        xg_c[g] = __half22float2(*(const __half2*)&xrow[g * 128]);
        xg_n[g] = xg_c[g];
    }

    int p = 0;
    for (int step = 0; step < Ss; step++) {
        if (step + 1 < Ss) {
            const __half* xb = xrow + (step + 1) * G4;
#pragma unroll
            for (int g = 0; g < 4; g++)
                xg_n[g] = __half22float2(*(const __half2*)&xb[g * 128]);
        }

        float acc[4][4];
#pragma unroll
        for (int g = 0; g < 4; g++)
#pragma unroll
            for (int j = 0; j < 4; j++) acc[g][j] = 0.f;
        uint32_t aAddr = p ? aAddr1 : aAddr0;
#pragma unroll
        for (int kt = 0; kt < 8; kt++) {
            uint32_t a[4];
            ldsm_x4(a[0], a[1], a[2], a[3], aAddr + kt * 32);
#pragma unroll
            for (int g = 0; g < 4; g++)
                mma_f16(acc[g], a, bf[kt][g]);
        }

        float iv0 = sigm_mufu(acc[0][0] + xg_c[0].x);
        float iv1 = sigm_mufu(acc[0][1] + xg_c[0].y);
        float fv0 = sigm_mufu(acc[1][0] + xg_c[1].x);
        float fv1 = sigm_mufu(acc[1][1] + xg_c[1].y);
        float gv0 = tanh_mufu(acc[2][0] + xg_c[2].x);
        float gv1 = tanh_mufu(acc[2][1] + xg_c[2].y);
        float ov0 = sigm_mufu(acc[3][0] + xg_c[3].x);
        float ov1 = sigm_mufu(acc[3][1] + xg_c[3].y);
        cc0 = fv0 * cc0 + iv0 * gv0;
        cc1 = fv1 * cc1 + iv1 * gv1;
        float h0 = ov0 * tanh_mufu(cc0);
        float h1 = ov1 * tanh_mufu(cc1);

        __half2 h01 = __floats2half2_rn(h0, h1);
        __half* hw = p ? hb0 : hb1;
        *(__half2*)&hw[gid * HB_STRIDE + col0] = h01;
        *(__half2*)&hsrow[step * Dd] = h01;
        __syncthreads();
        p ^= 1;
#pragma unroll
        for (int g = 0; g < 4; g++) xg_c[g] = xg_n[g];
    }
}

// ---------------- 4) MHA core (qkv fp16 in, att fp16 out) -------------------
#define QK_STRIDE 36
__global__ __launch_bounds__(128) void mha_kernel() {
    int bh = blockIdx.x;
    int b = bh >> 2, h = bh & 3;
    __shared__ float qs[Ss][QK_STRIDE], ks[Ss][QK_STRIDE], vs[Ss][QK_STRIDE];
    __shared__ float sc[Ss][52];
    int t = threadIdx.x;

    // load q|k|v: 600 8-half chunks, convert to fp32 smem
    for (int idx = t; idx < 600; idx += 128) {
        int which = idx / 200;
        int rem = idx - which * 200;
        int s = rem >> 2, c8 = (rem & 3) * 8;
        const __half2* src = (const __half2*)&g_qkvh[(b * Ss + s) * 384 + which * 128 + h * Ee + c8];
        float* dst = (which == 0) ? &qs[s][c8]
                   : (which == 1) ? &ks[s][c8] : &vs[s][c8];
#pragma unroll
        for (int i = 0; i < 4; i++) {
            float2 v = __half22float2(src[i]);
            dst[2 * i] = v.x; dst[2 * i + 1] = v.y;
        }
    }
    __syncthreads();

    const float scale = 0.17677669529663687f;
    if (t < 100) {
        int r = t >> 1;
        int c0 = (t & 1) * 25;
        float4 q[8];
#pragma unroll
        for (int i = 0; i < 8; i++) q[i] = *(float4*)&qs[r][i * 4];
        for (int c = c0; c < c0 + 25; c++) {
            float a = 0.f;
#pragma unroll
            for (int i = 0; i < 8; i++) {
                float4 k4 = *(float4*)&ks[c][i * 4];
                a += q[i].x * k4.x + q[i].y * k4.y + q[i].z * k4.z + q[i].w * k4.w;
            }
            sc[r][c] = a * scale;
        }
    }
    __syncthreads();
    if (t < Ss) {
        float mx = -3.4e38f;
        for (int c = 0; c < Ss; c++) mx = fmaxf(mx, sc[t][c]);
        float sm = 0.f;
        for (int c = 0; c < Ss; c++) { float e = __expf(sc[t][c] - mx); sc[t][c] = e; sm += e; }
        float inv = 1.f / sm;
        for (int c = 0; c < Ss; c++) sc[t][c] *= inv;
    }
    __syncthreads();
    int q4 = t & 7;
    for (int s = t >> 3; s < Ss; s += 16) {
        float4 acc = make_float4(0.f, 0.f, 0.f, 0.f);
        for (int c = 0; c < Ss; c++) {
            float a = sc[s][c];
            float4 v4 = *(float4*)&vs[c][q4 * 4];
            acc.x += a * v4.x; acc.y += a * v4.y;
            acc.z += a * v4.z; acc.w += a * v4.w;
        }
        __half* dst = &g_atth[(b * Ss + s) * Dd + h * Ee + q4 * 4];
        *(__half2*)&dst[0] = __floats2half2_rn(acc.x, acc.y);
        *(__half2*)&dst[2] = __floats2half2_rn(acc.z, acc.w);
    }
}

// ---------------- 5) short-term pooling -------------------------------------
__global__ __launch_bounds__(128) void shortpool_kernel() {
    int b = blockIdx.x;
    __shared__ float qv[Dd];
    __shared__ float sc[64];
    __shared__ float red4[4];
    int t = threadIdx.x;
    qv[t] = g_qvec[b * Dd + t];
    if (t >= Ss && t < 64) sc[t] = -3.4e38f;
    __syncthreads();
    if (t < Ss) {
        const float* row = &g_stm[(b * Ss + t) * Dd];
        float a = 0.f;
        for (int k = 0; k < Dd; k++) a += row[k] * qv[k];
        sc[t] = a;
    }
    __syncthreads();
    if (t < 64) {
        float v = sc[t];
#pragma unroll
        for (int ofs = 16; ofs >= 1; ofs >>= 1)
            v = fmaxf(v, __shfl_xor_sync(0xFFFFFFFFu, v, ofs));
        if ((t & 31) == 0) red4[t >> 5] = v;
    }
    __syncthreads();
    float mx = fmaxf(red4[0], red4[1]);
    float ev = (t < Ss) ? __expf(sc[t] - mx) : 0.f;
    if (t < 64) sc[t] = ev;
    __syncthreads();
    if (t < 64) {
        float v = sc[t];
#pragma unroll
        for (int ofs = 16; ofs >= 1; ofs >>= 1)
            v += __shfl_xor_sync(0xFFFFFFFFu, v, ofs);
        if ((t & 31) == 0) red4[2 + (t >> 5)] = v;
    }
    __syncthreads();
    float inv = 1.f / (red4[2] + red4[3]);
    float a = 0.f;
    for (int s = 0; s < Ss; s++) a += sc[s] * g_stm[(b * Ss + s) * Dd + t];
    float r = a * inv;
    g_short[b * Dd + t] = r;
    g_gateAh[b * G4 + 256 + t] = __float2half(r);
}

// ---------------- 6) long-term field attention ------------------------------
#define LT_STRIDE 36
__global__ __launch_bounds__(256) void longterm_kernel(const int* __restrict__ ltb,
                                                       const float* __restrict__ emb,
                                                       const float* __restrict__ Wt,
                                                       const float* __restrict__ bt) {
    int bi = blockIdx.x;
    int b = bi >> 2, fi = bi & 3;
    __shared__ int   ids[Ll];
    __shared__ float vecs[Ll][LT_STRIDE];
    __shared__ float sc[Ll];
    __shared__ float uv[Ee];
    __shared__ float part[8][Ee];
    __shared__ float red[256];
    int t = threadIdx.x;
    if (t < Ll) ids[t] = ltb[(b * Ll + t) * Ff + fi];
    __syncthreads();
    for (int idx = t; idx < Ll * 8; idx += 256) {
        int l = idx >> 3, q4 = idx & 7;
        *(float4*)&vecs[l][q4 * 4] = *(const float4*)&emb[ids[l] * Ee + q4 * 4];
    }
    {
        int e = t & 31, g = t >> 5;
        float a = 0.f;
        for (int k = g * 32; k < g * 32 + 32; k++)
            a += g_user_e[b * UE + k] * Wt[(fi * UE + k) * Ee + e];
        part[g][e] = a;
    }
    __syncthreads();
    if (t < Ee) {
        float a = bt[fi * Ee + t];
        for (int g = 0; g < 8; g++) a += part[g][t];
        uv[t] = a;
    }
    __syncthreads();
    if (t < Ll) {
        int mid = ids[t];
        bool keep = true;
        for (int j = 0; j < t; j++) if (ids[j] == mid) { keep = false; break; }
        float a = 0.f;
#pragma unroll
        for (int i = 0; i < 8; i++) {
            float4 v4 = *(float4*)&vecs[t][i * 4];
            float4 u4 = *(float4*)&uv[i * 4];
            a += v4.x * u4.x + v4.y * u4.y + v4.z * u4.z + v4.w * u4.w;
        }
        sc[t] = keep ? a : NEGV;
    }
    __syncthreads();
    red[t] = (t < Ll) ? sc[t] : -3.4e38f;
    __syncthreads();
    for (int ofs = 128; ofs >= 1; ofs >>= 1) {
        if (t < ofs) red[t] = fmaxf(red[t], red[t + ofs]);
        __syncthreads();
    }
    float mx = red[0];
    __syncthreads();
    float ev = (t < Ll) ? __expf(sc[t] - mx) : 0.f;
    if (t < Ll) sc[t] = ev;
    red[t] = ev;
    __syncthreads();
    for (int ofs = 128; ofs >= 1; ofs >>= 1) {
        if (t < ofs) red[t] += red[t + ofs];
        __syncthreads();
    }
    float inv = 1.f / red[0];
    __syncthreads();
    {
        int e = t & 31, g = t >> 5;
        float a = 0.f;
        for (int l = g; l < Ll; l += 8) a += sc[l] * vecs[l][e];
        part[g][e] = a;
    }
    __syncthreads();
    if (t < Ee) {
        float a = 0.f;
        for (int g = 0; g < 8; g++) a += part[g][t];
        float r = a * inv;
        g_long[b * Dd + fi * Ee + t] = r;
        g_gateAh[b * G4 + 384 + fi * Ee + t] = __float2half(r);
    }
}

// ---------------- 7) gate mix ------------------------------------------------
__global__ __launch_bounds__(256) void gatemix_kernel(float* __restrict__ out) {
    int i = blockIdx.x * 256 + threadIdx.x;
    float g = sigm(g_gz[i]);
    out[i] = (1.f - g) * g_long[i] + g * g_short[i];
}

// ---------------- host ------------------------------------------------------
static void* symv(const void* s) {
    void* p = nullptr;
    cudaGetSymbolAddress(&p, s);
    return p;
}

extern "C" void kernel_launch(void* const* d_in, const int* in_sizes, int n_in,
                              void* d_out, int out_size) {
    const int*   up     = (const int*)d_in[0];
    const int*   stb    = (const int*)d_in[1];
    const int*   ltb    = (const int*)d_in[2];
    const float* emb    = (const float*)d_in[3];
    const float* lstm_W = (const float*)d_in[4];
    const float* lstm_U = (const float*)d_in[5];
    const float* lstm_b = (const float*)d_in[6];
    const float* Wq     = (const float*)d_in[7];
    const float* Wk     = (const float*)d_in[8];
    const float* Wv     = (const float*)d_in[9];
    const float* Wo     = (const float*)d_in[10];
    const float* W1     = (const float*)d_in[11];
    const float* b1     = (const float*)d_in[12];
    const float* Wt     = (const float*)d_in[13];
    const float* bt     = (const float*)d_in[14];
    const float* Wu     = (const float*)d_in[15];
    const float* bu     = (const float*)d_in[16];
    const float* Wsg    = (const float*)d_in[17];
    const float* bsg    = (const float*)d_in[18];
    const float* Wl     = (const float*)d_in[19];
    const float* bl     = (const float*)d_in[20];
    float* out = (float*)d_out;

    __half* p_gateAh = (__half*)symv(g_gateAh);
    __half* p_stxh   = (__half*)symv(g_stxh);
    __half* p_xWh    = (__half*)symv(g_xWh);
    __half* p_hsh    = (__half*)symv(g_hsh);
    __half* p_qkvh   = (__half*)symv(g_qkvh);
    __half* p_atth   = (__half*)symv(g_atth);
    float*  p_stm    = (float*)symv(g_stm);
    float*  p_qvec   = (float*)symv(g_qvec);
    float*  p_gz     = (float*)symv(g_gz);
    __half* p_Whr    = (__half*)symv(g_Whr);
    __half* p_Whqkv  = (__half*)symv(g_Whqkv);
    __half* p_Whor   = (__half*)symv(g_Whor);
    __half* p_Wh1    = (__half*)symv(g_Wh1);
    __half* p_Whg    = (__half*)symv(g_Whg);
    float*  p_bg     = (float*)symv(g_bg);

    const int MBS = Bb * Ss;  // 51200

    cudaFuncSetAttribute(lstm_mma_kernel,
                         cudaFuncAttributeMaxDynamicSharedMemorySize,
                         LSTM_SMEM_BYTES);
    cudaFuncSetAttribute(gemm_f16,
                         cudaFuncAttributeMaxDynamicSharedMemorySize,
                         GEMM_SMEM_BYTES);

    // 1) combined prep (gathers + all repacks)
    {
        int total = Bb * Ss * Dd + Bb * UE + G4 * Dd + G4 * Dd + 384 * Dd
                  + Dd * Dd + Dd * UE + Dd * G4 + Dd;
        prep_kernel<<<(total + 255) / 256, 256>>>(
            up, stb, emb, lstm_U, lstm_W, Wq, Wk, Wv, Wo, W1, Wu, Wsg, Wl,
            bu, bsg, bl);
    }
    // 2) xW = stx @ lstm_W + b  -> fp16
    gemm_f16<<<dim3(G4 / 128, MBS / 128), 256, GEMM_SMEM_BYTES>>>(
        p_stxh, p_Whr, lstm_b, nullptr, p_xWh, MBS, G4, Dd, Dd);
    // 3) LSTM recurrence
    lstm_mma_kernel<<<Bb / LSTM_ROWS, 512, LSTM_SMEM_BYTES>>>(p_xWh, p_hsh);
    // 4) fused QKV projection -> fp16
    gemm_f16<<<dim3(384 / 128, MBS / 128), 256, GEMM_SMEM_BYTES>>>(
        p_hsh, p_Whqkv, nullptr, nullptr, p_qkvh, MBS, 384, Dd, Dd);
    // 5) attention core + output projection (stm fp32)
    mha_kernel<<<Bb * Ff, 128>>>();
    gemm_f16<<<dim3(Dd / 128, MBS / 128), 256, GEMM_SMEM_BYTES>>>(
        p_atth, p_Whor, nullptr, p_stm, nullptr, MBS, Dd, Dd, Dd);
    // 6) pooling query + short-term pooling
    gemm_f16<<<dim3(Dd / 128, Bb / 128), 256, GEMM_SMEM_BYTES>>>(
        p_gateAh, p_Wh1, b1, p_qvec, nullptr, Bb, Dd, UE, G4);
    shortpool_kernel<<<Bb, 128>>>();
    // 7) long-term field attention
    longterm_kernel<<<Bb * Ff, 256>>>(ltb, emb, Wt, bt);
    // 8) gate preact GEMM + mix
    gemm_f16<<<dim3(Dd / 128, Bb / 128), 256, GEMM_SMEM_BYTES>>>(
        p_gateAh, p_Whg, p_bg, p_gz, nullptr, Bb, Dd, G4, G4);
    gatemix_kernel<<<(Bb * Dd) / 256, 256>>>(out);
}